// round 7
// baseline (speedup 1.0000x reference)
#include <cuda_runtime.h>

#define T 1600
#define BH 64
#define HD 32
// softmax scale * log2(e): scores are computed in exp2 domain
#define QSCALE (0.17677669529663687f * 1.4426950408889634f)

// Pre-fragmented Q/K scratch (tf32-rounded fp32), written by kernel 1 in mma
// fragment order so kernel 2 loads fragments with coalesced LDG.
// Qf: [bh][rt=t/16][kk=d/8][lane][reg]   reg = ((d>>2)&1)*2 + ((t>>3)&1)
// Kf: [bh][si=t/64][nt=(t/8)%8][kk][lane][b]  b = (d>>2)&1
static __device__ float g_Qf[(size_t)BH * 100 * 4 * 32 * 4];
static __device__ float g_Kf[(size_t)BH * 25 * 8 * 4 * 32 * 2];

__device__ __forceinline__ unsigned f2tf32(float f) {
    unsigned r;
    asm("cvt.rna.tf32.f32 %0, %1;" : "=r"(r) : "f"(f));
    return r;
}

__device__ __forceinline__ float ex2(float x) {
    float y;
    asm("ex2.approx.ftz.f32 %0, %1;" : "=f"(y) : "f"(x));
    return y;
}

__device__ __forceinline__ void mma_tf32(float c[4], const unsigned a[4], const unsigned b[2]) {
    asm volatile(
        "mma.sync.aligned.m16n8k8.row.col.f32.tf32.tf32.f32 "
        "{%0,%1,%2,%3}, {%4,%5,%6,%7}, {%8,%9}, {%0,%1,%2,%3};\n"
        : "+f"(c[0]), "+f"(c[1]), "+f"(c[2]), "+f"(c[3])
        : "r"(a[0]), "r"(a[1]), "r"(a[2]), "r"(a[3]), "r"(b[0]), "r"(b[1]));
}

__device__ __forceinline__ void store_qfrag(int bh, int t, int d, float v) {
    const int rt = t >> 4, gid = t & 7, rlo = (t >> 3) & 1;
    const int kk = d >> 3, tig = d & 3, rhi = (d >> 2) & 1;
    g_Qf[((((size_t)bh * 100 + rt) * 4 + kk) * 32 + gid * 4 + tig) * 4 + rhi * 2 + rlo] = v;
}

__device__ __forceinline__ void store_kfrag(int bh, int t, int d, float v) {
    const int si = t >> 6, nt = (t >> 3) & 7, gid = t & 7;
    const int kk = d >> 3, tig = d & 3, b = (d >> 2) & 1;
    g_Kf[((((size_t)bh * 25 + si) * 8 + nt) * 4 + kk) * 64 + (gid * 4 + tig) * 2 + b] = v;
}

// ===================== Kernel 1: LayerNorm + QKV projection (Q,K only) =====================
#define XS_STRIDE 72
#define WS_STRIDE 68
#define K1_SMEM_FLOATS (256 * XS_STRIDE + 128 * WS_STRIDE + 256 + 256 + 64 + 64)

__global__ void __launch_bounds__(256) ln_qkv_kernel(
    const float* __restrict__ feat, const float* __restrict__ ln_w,
    const float* __restrict__ ln_b, const float* __restrict__ qkv_w,
    const float* __restrict__ qkv_b)
{
    extern __shared__ float sm[];
    float* xs  = sm;                        // [256][72] raw x, [c][t]
    float* ws  = xs + 256 * XS_STRIDE;      // [128][68] tf32 W chunk, [n][c]
    float* lw  = ws + 128 * WS_STRIDE;      // [256]
    float* lb  = lw + 256;                  // [256]
    float* mus = lb + 256;                  // [64]
    float* rss = mus + 64;                  // [64]

    const int tid = threadIdx.x;
    const int n0 = blockIdx.x * 128;        // 0,128 -> Q ; 256,384 -> K
    const int tb = blockIdx.y;              // 0..199
    const int b  = tb / 25;
    const int t0 = (tb % 25) * 64;

    {
        const float* src = feat + ((size_t)b * 256) * T + t0;
        const int c4 = (tid & 15) * 4;
        #pragma unroll 4
        for (int c = tid >> 4; c < 256; c += 16) {
            const float4 v = *(const float4*)(src + (size_t)c * T + c4);
            float* d = xs + c * XS_STRIDE + c4;
            d[0] = v.x; d[1] = v.y; d[2] = v.z; d[3] = v.w;
        }
        lw[tid] = ln_w[tid];
        lb[tid] = ln_b[tid];
    }
    __syncthreads();

    {
        const int t = tid >> 2, g = tid & 3;
        float s = 0.f, sq = 0.f;
        for (int c = g; c < 256; c += 4) {
            const float v = xs[c * XS_STRIDE + t];
            s += v; sq += v * v;
        }
        s += __shfl_xor_sync(~0u, s, 1); sq += __shfl_xor_sync(~0u, sq, 1);
        s += __shfl_xor_sync(~0u, s, 2); sq += __shfl_xor_sync(~0u, sq, 2);
        if (g == 0) {
            const float mu = s * (1.f / 256.f);
            mus[t] = mu;
            rss[t] = rsqrtf(sq * (1.f / 256.f) - mu * mu + 1e-6f);
        }
    }
    __syncthreads();

    const int warp = tid >> 5, lane = tid & 31;
    const int wm = warp >> 1, wn = warp & 1;
    const int gid = lane >> 2, tig = lane & 3;
    const int tl = wm * 16 + gid;
    const float mu0 = mus[tl], rs0 = rss[tl], mu1 = mus[tl + 8], rs1 = rss[tl + 8];

    float acc[8][4];
    #pragma unroll
    for (int i = 0; i < 8; i++) {
        #pragma unroll
        for (int j = 0; j < 4; j++) acc[i][j] = 0.f;
    }

    for (int kc = 0; kc < 4; kc++) {
        const int c0 = kc * 64;
        __syncthreads();
        {
            const int c4 = (tid & 15) * 4;
            const float* wsrc = qkv_w + (size_t)n0 * 256 + c0 + c4;
            #pragma unroll
            for (int n = tid >> 4; n < 128; n += 16) {
                const float4 v = *(const float4*)(wsrc + (size_t)n * 256);
                float* d = ws + n * WS_STRIDE + c4;
                d[0] = __uint_as_float(f2tf32(v.x));
                d[1] = __uint_as_float(f2tf32(v.y));
                d[2] = __uint_as_float(f2tf32(v.z));
                d[3] = __uint_as_float(f2tf32(v.w));
            }
        }
        __syncthreads();
        #pragma unroll
        for (int kk = 0; kk < 8; kk++) {
            const int c = c0 + kk * 8 + tig;
            const float wc = lw[c], bc = lb[c], wc4 = lw[c + 4], bc4 = lb[c + 4];
            unsigned a[4];
            a[0] = f2tf32((xs[c * XS_STRIDE + tl]           - mu0) * rs0 * wc  + bc);
            a[1] = f2tf32((xs[c * XS_STRIDE + tl + 8]       - mu1) * rs1 * wc  + bc);
            a[2] = f2tf32((xs[(c + 4) * XS_STRIDE + tl]     - mu0) * rs0 * wc4 + bc4);
            a[3] = f2tf32((xs[(c + 4) * XS_STRIDE + tl + 8] - mu1) * rs1 * wc4 + bc4);
            #pragma unroll
            for (int nt = 0; nt < 8; nt++) {
                const int nl = wn * 64 + nt * 8 + gid;
                unsigned bf[2];
                bf[0] = __float_as_uint(ws[nl * WS_STRIDE + kk * 8 + tig]);
                bf[1] = __float_as_uint(ws[nl * WS_STRIDE + kk * 8 + tig + 4]);
                mma_tf32(acc[nt], a, bf);
            }
        }
    }

    const bool is_q = (n0 < 256);
    const int trow = t0 + tl;
    #pragma unroll
    for (int nt = 0; nt < 8; nt++) {
        const int ng = n0 + wn * 64 + nt * 8 + 2 * tig;
        const int nq = is_q ? ng : (ng - 256);
        const int h = nq >> 5, d = nq & 31;
        const int bh = b * 8 + h;
        const float bias0 = qkv_b[ng], bias1 = qkv_b[ng + 1];
        float v0 = acc[nt][0] + bias0, v1 = acc[nt][1] + bias1;
        float v2 = acc[nt][2] + bias0, v3 = acc[nt][3] + bias1;
        if (is_q) {
            v0 *= QSCALE; v1 *= QSCALE; v2 *= QSCALE; v3 *= QSCALE;
            store_qfrag(bh, trow,     d,     __uint_as_float(f2tf32(v0)));
            store_qfrag(bh, trow,     d + 1, __uint_as_float(f2tf32(v1)));
            store_qfrag(bh, trow + 8, d,     __uint_as_float(f2tf32(v2)));
            store_qfrag(bh, trow + 8, d + 1, __uint_as_float(f2tf32(v3)));
        } else {
            store_kfrag(bh, trow,     d,     __uint_as_float(f2tf32(v0)));
            store_kfrag(bh, trow,     d + 1, __uint_as_float(f2tf32(v1)));
            store_kfrag(bh, trow + 8, d,     __uint_as_float(f2tf32(v2)));
            store_kfrag(bh, trow + 8, d + 1, __uint_as_float(f2tf32(v3)));
        }
    }
}

// ===================== Kernel 2: direct-LDG K, group-granular pipeline ============
// 128 thr / 4 warps, 2x2 split: wm -> 32 rows (2 m-frags), wn -> 32 of 64 chunk
// cols. No K smem; K fragments LDG'd from fragment-ordered gmem into a 2x4-float2
// register double buffer at 8-col-group granularity (4 independent LDG.64 in
// flight). kk accumulation split into two chains (depth 2) merged by FADD before
// ex2. 100 groups per pass; pass 1 sums exp2(s), pass 2 recomputes + writes.
__global__ void __launch_bounds__(128, 5) attn_kernel(float* __restrict__ out)
{
    __shared__ float red[2][64];

    const int tid = threadIdx.x;
    const int warp = tid >> 5, lane = tid & 31;
    const int gid = lane >> 2, tig = lane & 3;
    const int wm = warp >> 1, wn = warp & 1;
    const int bh = blockIdx.y;
    const int t0 = blockIdx.x * 64;

    // A fragments: 2 m-frags (32 rows), constant for whole kernel (8x LDG.128)
    unsigned afr[2][4][4];
    #pragma unroll
    for (int mf = 0; mf < 2; mf++) {
        const int rt = blockIdx.x * 4 + wm * 2 + mf;
        const float4* qf = (const float4*)g_Qf + ((size_t)bh * 100 + rt) * 4 * 32 + lane;
        #pragma unroll
        for (int kk = 0; kk < 4; kk++) {
            const float4 v = qf[kk * 32];
            afr[mf][kk][0] = __float_as_uint(v.x);
            afr[mf][kk][1] = __float_as_uint(v.y);
            afr[mf][kk][2] = __float_as_uint(v.z);
            afr[mf][kk][3] = __float_as_uint(v.w);
        }
    }

    const float2* kw = (const float2*)g_Kf + (size_t)bh * 25 * 1024 + lane;

    float2 kb[2][4];            // [buf][kk] one 8-col group
    float sums[4] = {0.f, 0.f, 0.f, 0.f};
    float inv[4];

    // group g in 0..99: si = g>>2, ntg = wn*4 + (g&3)
    #define LOADG(buf, g) {                                                   \
        const float2* p_ = kw + (size_t)((g) >> 2) * 1024                     \
                              + (wn * 4 + ((g) & 3)) * 128;                   \
        kb[buf][0] = p_[0];  kb[buf][1] = p_[32];                             \
        kb[buf][2] = p_[64]; kb[buf][3] = p_[96]; }

    #define MMA_GROUP(buf)                                                    \
        unsigned bfr[4][2];                                                   \
        _Pragma("unroll")                                                     \
        for (int kk = 0; kk < 4; kk++) {                                      \
            bfr[kk][0] = __float_as_uint(kb[buf][kk].x);                      \
            bfr[kk][1] = __float_as_uint(kb[buf][kk].y);                      \
        }                                                                     \
        float cA0[4] = {0.f,0.f,0.f,0.f}, cB0[4] = {0.f,0.f,0.f,0.f};         \
        float cA1[4] = {0.f,0.f,0.f,0.f}, cB1[4] = {0.f,0.f,0.f,0.f};         \
        mma_tf32(cA0, afr[0][0], bfr[0]); mma_tf32(cA1, afr[1][0], bfr[0]);   \
        mma_tf32(cB0, afr[0][2], bfr[2]); mma_tf32(cB1, afr[1][2], bfr[2]);   \
        mma_tf32(cA0, afr[0][1], bfr[1]); mma_tf32(cA1, afr[1][1], bfr[1]);   \
        mma_tf32(cB0, afr[0][3], bfr[3]); mma_tf32(cB1, afr[1][3], bfr[3]);

    // ---------------- pass 1: row sums of exp2(scores) ----------------
    #define P1_BODY(buf) {                                                    \
        MMA_GROUP(buf)                                                        \
        sums[0] += ex2(cA0[0] + cB0[0]) + ex2(cA0[1] + cB0[1]);               \
        sums[1] += ex2(cA0[2] + cB0[2]) + ex2(cA0[3] + cB0[3]);               \
        sums[2] += ex2(cA1[0] + cB1[0]) + ex2(cA1[1] + cB1[1]);               \
        sums[3] += ex2(cA1[2] + cB1[2]) + ex2(cA1[3] + cB1[3]); }

    LOADG(0, 0)
    for (int gp = 0; gp < 50; gp++) {
        const int g0 = 2 * gp, g1 = g0 + 1;
        LOADG(1, g1)
        { P1_BODY(0) }
        LOADG(0, (g1 + 1 == 100) ? 0 : g1 + 1)   // wrap: prefetch group 0 for pass 2
        { P1_BODY(1) }
    }

    // ---------------- cross-warp row-sum reduction ----------------
    #pragma unroll
    for (int i = 0; i < 4; i++) {
        sums[i] += __shfl_xor_sync(~0u, sums[i], 1);
        sums[i] += __shfl_xor_sync(~0u, sums[i], 2);
    }
    if (tig == 0) {
        #pragma unroll
        for (int mf = 0; mf < 2; mf++) {
            red[wn][wm * 32 + mf * 16 + gid]     = sums[mf * 2];
            red[wn][wm * 32 + mf * 16 + 8 + gid] = sums[mf * 2 + 1];
        }
    }
    __syncthreads();
    #pragma unroll
    for (int mf = 0; mf < 2; mf++) {
        const int lr0 = wm * 32 + mf * 16 + gid;
        inv[mf * 2]     = 1.0f / (red[0][lr0] + red[1][lr0]);
        inv[mf * 2 + 1] = 1.0f / (red[0][lr0 + 8] + red[1][lr0 + 8]);
    }

    // ---------------- pass 2: recompute, normalize, stream out ----------------
    float* const obase = out + ((size_t)bh * T + t0 + wm * 32 + gid) * T + 2 * tig;

    #define P2_BODY(buf, g) {                                                 \
        MMA_GROUP(buf)                                                        \
        float* pp = obase + ((g) >> 2) * 64 + (wn * 4 + ((g) & 3)) * 8;       \
        *(float2*)pp = make_float2(ex2(cA0[0] + cB0[0]) * inv[0],             \
                                   ex2(cA0[1] + cB0[1]) * inv[0]);            \
        *(float2*)(pp + 8 * T)  = make_float2(ex2(cA0[2] + cB0[2]) * inv[1],  \
                                              ex2(cA0[3] + cB0[3]) * inv[1]); \
        *(float2*)(pp + 16 * T) = make_float2(ex2(cA1[0] + cB1[0]) * inv[2],  \
                                              ex2(cA1[1] + cB1[1]) * inv[2]); \
        *(float2*)(pp + 24 * T) = make_float2(ex2(cA1[2] + cB1[2]) * inv[3],  \
                                              ex2(cA1[3] + cB1[3]) * inv[3]); }

    for (int gp = 0; gp < 50; gp++) {
        const int g0 = 2 * gp, g1 = g0 + 1;
        LOADG(1, g1)
        { P2_BODY(0, g0) }
        if (g1 < 99) LOADG(0, g1 + 1)
        { P2_BODY(1, g1) }
    }

    #undef LOADG
    #undef MMA_GROUP
    #undef P1_BODY
    #undef P2_BODY
}

extern "C" void kernel_launch(void* const* d_in, const int* in_sizes, int n_in,
                              void* d_out, int out_size)
{
    (void)in_sizes; (void)n_in; (void)out_size;
    const float* feat  = (const float*)d_in[0];
    const float* ln_w  = (const float*)d_in[1];
    const float* ln_b  = (const float*)d_in[2];
    const float* qkv_w = (const float*)d_in[3];
    const float* qkv_b = (const float*)d_in[4];
    float* out = (float*)d_out;

    cudaFuncSetAttribute(ln_qkv_kernel, cudaFuncAttributeMaxDynamicSharedMemorySize,
                         K1_SMEM_FLOATS * 4);

    ln_qkv_kernel<<<dim3(4, 200), 256, K1_SMEM_FLOATS * 4>>>(feat, ln_w, ln_b, qkv_w, qkv_b);
    attn_kernel<<<dim3(25, 64), 128>>>(out);
}

// round 8
// speedup vs baseline: 1.0730x; 1.0730x over previous
#include <cuda_runtime.h>

#define T 1600
#define BH 64
#define HD 32
// softmax scale * log2(e): scores are computed in exp2 domain
#define QSCALE (0.17677669529663687f * 1.4426950408889634f)

// Pre-fragmented Q/K scratch (tf32-rounded fp32), written by kernel 1 in mma
// fragment order so kernel 2 loads fragments with coalesced LDG.
// Qf: [bh][rt=t/16][kk=d/8][lane][reg]   reg = ((d>>2)&1)*2 + ((t>>3)&1)
// Kf: [bh][si=t/64][nt=(t/8)%8][lane][kk][b]  -> per-thread 8 contiguous floats
//     (kk0b0,kk0b1,kk1b0,kk1b1,kk2b0,kk2b1,kk3b0,kk3b1) = 2 x float4
static __device__ float g_Qf[(size_t)BH * 100 * 4 * 32 * 4];
static __device__ float g_Kf[(size_t)BH * 25 * 8 * 32 * 8];

__device__ __forceinline__ unsigned f2tf32(float f) {
    unsigned r;
    asm("cvt.rna.tf32.f32 %0, %1;" : "=r"(r) : "f"(f));
    return r;
}

__device__ __forceinline__ float ex2(float x) {
    float y;
    asm("ex2.approx.ftz.f32 %0, %1;" : "=f"(y) : "f"(x));
    return y;
}

__device__ __forceinline__ void mma_tf32(float c[4], const unsigned a[4], const unsigned b[2]) {
    asm volatile(
        "mma.sync.aligned.m16n8k8.row.col.f32.tf32.tf32.f32 "
        "{%0,%1,%2,%3}, {%4,%5,%6,%7}, {%8,%9}, {%0,%1,%2,%3};\n"
        : "+f"(c[0]), "+f"(c[1]), "+f"(c[2]), "+f"(c[3])
        : "r"(a[0]), "r"(a[1]), "r"(a[2]), "r"(a[3]), "r"(b[0]), "r"(b[1]));
}

__device__ __forceinline__ void store_qfrag(int bh, int t, int d, float v) {
    const int rt = t >> 4, gid = t & 7, rlo = (t >> 3) & 1;
    const int kk = d >> 3, tig = d & 3, rhi = (d >> 2) & 1;
    g_Qf[((((size_t)bh * 100 + rt) * 4 + kk) * 32 + gid * 4 + tig) * 4 + rhi * 2 + rlo] = v;
}

__device__ __forceinline__ void store_kfrag(int bh, int t, int d, float v) {
    const int si = t >> 6, nt = (t >> 3) & 7, gid = t & 7;
    const int kk = d >> 3, tig = d & 3, b = (d >> 2) & 1;
    g_Kf[(((size_t)bh * 25 + si) * 8 + nt) * 256 + (gid * 4 + tig) * 8 + kk * 2 + b] = v;
}

// ===================== Kernel 1: LayerNorm + QKV projection (Q,K only) =====================
#define XS_STRIDE 72
#define WS_STRIDE 68
#define K1_SMEM_FLOATS (256 * XS_STRIDE + 128 * WS_STRIDE + 256 + 256 + 64 + 64)

__global__ void __launch_bounds__(256) ln_qkv_kernel(
    const float* __restrict__ feat, const float* __restrict__ ln_w,
    const float* __restrict__ ln_b, const float* __restrict__ qkv_w,
    const float* __restrict__ qkv_b)
{
    extern __shared__ float sm[];
    float* xs  = sm;                        // [256][72] raw x, [c][t]
    float* ws  = xs + 256 * XS_STRIDE;      // [128][68] tf32 W chunk, [n][c]
    float* lw  = ws + 128 * WS_STRIDE;      // [256]
    float* lb  = lw + 256;                  // [256]
    float* mus = lb + 256;                  // [64]
    float* rss = mus + 64;                  // [64]

    const int tid = threadIdx.x;
    const int n0 = blockIdx.x * 128;        // 0,128 -> Q ; 256,384 -> K
    const int tb = blockIdx.y;              // 0..199
    const int b  = tb / 25;
    const int t0 = (tb % 25) * 64;

    {
        const float* src = feat + ((size_t)b * 256) * T + t0;
        const int c4 = (tid & 15) * 4;
        #pragma unroll 4
        for (int c = tid >> 4; c < 256; c += 16) {
            const float4 v = *(const float4*)(src + (size_t)c * T + c4);
            float* d = xs + c * XS_STRIDE + c4;
            d[0] = v.x; d[1] = v.y; d[2] = v.z; d[3] = v.w;
        }
        lw[tid] = ln_w[tid];
        lb[tid] = ln_b[tid];
    }
    __syncthreads();

    {
        const int t = tid >> 2, g = tid & 3;
        float s = 0.f, sq = 0.f;
        for (int c = g; c < 256; c += 4) {
            const float v = xs[c * XS_STRIDE + t];
            s += v; sq += v * v;
        }
        s += __shfl_xor_sync(~0u, s, 1); sq += __shfl_xor_sync(~0u, sq, 1);
        s += __shfl_xor_sync(~0u, s, 2); sq += __shfl_xor_sync(~0u, sq, 2);
        if (g == 0) {
            const float mu = s * (1.f / 256.f);
            mus[t] = mu;
            rss[t] = rsqrtf(sq * (1.f / 256.f) - mu * mu + 1e-6f);
        }
    }
    __syncthreads();

    const int warp = tid >> 5, lane = tid & 31;
    const int wm = warp >> 1, wn = warp & 1;
    const int gid = lane >> 2, tig = lane & 3;
    const int tl = wm * 16 + gid;
    const float mu0 = mus[tl], rs0 = rss[tl], mu1 = mus[tl + 8], rs1 = rss[tl + 8];

    float acc[8][4];
    #pragma unroll
    for (int i = 0; i < 8; i++) {
        #pragma unroll
        for (int j = 0; j < 4; j++) acc[i][j] = 0.f;
    }

    for (int kc = 0; kc < 4; kc++) {
        const int c0 = kc * 64;
        __syncthreads();
        {
            const int c4 = (tid & 15) * 4;
            const float* wsrc = qkv_w + (size_t)n0 * 256 + c0 + c4;
            #pragma unroll
            for (int n = tid >> 4; n < 128; n += 16) {
                const float4 v = *(const float4*)(wsrc + (size_t)n * 256);
                float* d = ws + n * WS_STRIDE + c4;
                d[0] = __uint_as_float(f2tf32(v.x));
                d[1] = __uint_as_float(f2tf32(v.y));
                d[2] = __uint_as_float(f2tf32(v.z));
                d[3] = __uint_as_float(f2tf32(v.w));
            }
        }
        __syncthreads();
        #pragma unroll
        for (int kk = 0; kk < 8; kk++) {
            const int c = c0 + kk * 8 + tig;
            const float wc = lw[c], bc = lb[c], wc4 = lw[c + 4], bc4 = lb[c + 4];
            unsigned a[4];
            a[0] = f2tf32((xs[c * XS_STRIDE + tl]           - mu0) * rs0 * wc  + bc);
            a[1] = f2tf32((xs[c * XS_STRIDE + tl + 8]       - mu1) * rs1 * wc  + bc);
            a[2] = f2tf32((xs[(c + 4) * XS_STRIDE + tl]     - mu0) * rs0 * wc4 + bc4);
            a[3] = f2tf32((xs[(c + 4) * XS_STRIDE + tl + 8] - mu1) * rs1 * wc4 + bc4);
            #pragma unroll
            for (int nt = 0; nt < 8; nt++) {
                const int nl = wn * 64 + nt * 8 + gid;
                unsigned bf[2];
                bf[0] = __float_as_uint(ws[nl * WS_STRIDE + kk * 8 + tig]);
                bf[1] = __float_as_uint(ws[nl * WS_STRIDE + kk * 8 + tig + 4]);
                mma_tf32(acc[nt], a, bf);
            }
        }
    }

    const bool is_q = (n0 < 256);
    const int trow = t0 + tl;
    #pragma unroll
    for (int nt = 0; nt < 8; nt++) {
        const int ng = n0 + wn * 64 + nt * 8 + 2 * tig;
        const int nq = is_q ? ng : (ng - 256);
        const int h = nq >> 5, d = nq & 31;
        const int bh = b * 8 + h;
        const float bias0 = qkv_b[ng], bias1 = qkv_b[ng + 1];
        float v0 = acc[nt][0] + bias0, v1 = acc[nt][1] + bias1;
        float v2 = acc[nt][2] + bias0, v3 = acc[nt][3] + bias1;
        if (is_q) {
            v0 *= QSCALE; v1 *= QSCALE; v2 *= QSCALE; v3 *= QSCALE;
            store_qfrag(bh, trow,     d,     __uint_as_float(f2tf32(v0)));
            store_qfrag(bh, trow,     d + 1, __uint_as_float(f2tf32(v1)));
            store_qfrag(bh, trow + 8, d,     __uint_as_float(f2tf32(v2)));
            store_qfrag(bh, trow + 8, d + 1, __uint_as_float(f2tf32(v3)));
        } else {
            store_kfrag(bh, trow,     d,     __uint_as_float(f2tf32(v0)));
            store_kfrag(bh, trow,     d + 1, __uint_as_float(f2tf32(v1)));
            store_kfrag(bh, trow + 8, d,     __uint_as_float(f2tf32(v2)));
            store_kfrag(bh, trow + 8, d + 1, __uint_as_float(f2tf32(v3)));
        }
    }
}

// ===================== Kernel 2: direct-LDG K, half-chunk register pipeline ======
// r6 structure (best): 128 thr / 4 warps, 2x2 split; wm -> 32 rows (2 m-frags),
// wn -> 32 of 64 chunk cols. K fragments LDG'd straight from fragment-ordered
// gmem into a 2 x 4-float4 register double buffer at HALF-CHUNK granularity
// (4 independent LDG.128 in flight, one half-chunk of cover before reuse).
// Contiguous per-thread fragment packing makes each group load one LDG.128.
__global__ void __launch_bounds__(128, 5) attn_kernel(float* __restrict__ out)
{
    __shared__ float red[2][64];

    const int tid = threadIdx.x;
    const int warp = tid >> 5, lane = tid & 31;
    const int gid = lane >> 2, tig = lane & 3;
    const int wm = warp >> 1, wn = warp & 1;
    const int bh = blockIdx.y;
    const int t0 = blockIdx.x * 64;

    // A fragments: 2 m-frags (32 rows), constant for whole kernel (8x LDG.128)
    unsigned afr[2][4][4];
    #pragma unroll
    for (int mf = 0; mf < 2; mf++) {
        const int rt = blockIdx.x * 4 + wm * 2 + mf;
        const float4* qf = (const float4*)g_Qf + ((size_t)bh * 100 + rt) * 4 * 32 + lane;
        #pragma unroll
        for (int kk = 0; kk < 4; kk++) {
            const float4 v = qf[kk * 32];
            afr[mf][kk][0] = __float_as_uint(v.x);
            afr[mf][kk][1] = __float_as_uint(v.y);
            afr[mf][kk][2] = __float_as_uint(v.z);
            afr[mf][kk][3] = __float_as_uint(v.w);
        }
    }

    // per-thread K fragment base; chunk = 512 float4, nt-group = 64 float4
    const float4* kw = (const float4*)g_Kf + (size_t)bh * 25 * 512 + lane * 2;

    float4 kb[2][4];      // [buf][group*2 + j]: 2 nt-groups per half-chunk
    float sums[4] = {0.f, 0.f, 0.f, 0.f};
    float inv[4];

    // load half-chunk p (nt groups wn*4+2p, wn*4+2p+1) of chunk si into kb[buf]
    #define LOADP(buf, si, p) {                                               \
        const float4* p_ = kw + (size_t)(si) * 512 + (wn * 4 + (p) * 2) * 64; \
        kb[buf][0] = p_[0];  kb[buf][1] = p_[1];                              \
        kb[buf][2] = p_[64]; kb[buf][3] = p_[65]; }

    // compute one 8-col group from two float4s; c0 (rows wm*32..+15), c1 (+16..31)
    #define MMA_GROUP(va, vb)                                                 \
        unsigned bfr[4][2];                                                   \
        bfr[0][0] = __float_as_uint((va).x); bfr[0][1] = __float_as_uint((va).y); \
        bfr[1][0] = __float_as_uint((va).z); bfr[1][1] = __float_as_uint((va).w); \
        bfr[2][0] = __float_as_uint((vb).x); bfr[2][1] = __float_as_uint((vb).y); \
        bfr[3][0] = __float_as_uint((vb).z); bfr[3][1] = __float_as_uint((vb).w); \
        float c0[4] = {0.f,0.f,0.f,0.f}, c1[4] = {0.f,0.f,0.f,0.f};           \
        _Pragma("unroll")                                                     \
        for (int kk = 0; kk < 4; kk++) mma_tf32(c0, afr[0][kk], bfr[kk]);     \
        _Pragma("unroll")                                                     \
        for (int kk = 0; kk < 4; kk++) mma_tf32(c1, afr[1][kk], bfr[kk]);

    // ---------------- pass 1: row sums of exp2(scores) ----------------
    #define P1_GROUP(va, vb) {                                                \
        MMA_GROUP(va, vb)                                                     \
        sums[0] += ex2(c0[0]) + ex2(c0[1]);                                   \
        sums[1] += ex2(c0[2]) + ex2(c0[3]);                                   \
        sums[2] += ex2(c1[0]) + ex2(c1[1]);                                   \
        sums[3] += ex2(c1[2]) + ex2(c1[3]); }

    LOADP(0, 0, 0)
    LOADP(1, 0, 1)
    for (int ci = 0; ci < 25; ci++) {
        const int nsi = (ci == 24) ? 0 : ci + 1;   // wrap: prefetch chunk 0 for pass 2
        { P1_GROUP(kb[0][0], kb[0][1]) }
        { P1_GROUP(kb[0][2], kb[0][3]) }
        LOADP(0, nsi, 0)
        { P1_GROUP(kb[1][0], kb[1][1]) }
        { P1_GROUP(kb[1][2], kb[1][3]) }
        LOADP(1, nsi, 1)
    }

    // ---------------- cross-warp row-sum reduction ----------------
    #pragma unroll
    for (int i = 0; i < 4; i++) {
        sums[i] += __shfl_xor_sync(~0u, sums[i], 1);
        sums[i] += __shfl_xor_sync(~0u, sums[i], 2);
    }
    if (tig == 0) {
        #pragma unroll
        for (int mf = 0; mf < 2; mf++) {
            red[wn][wm * 32 + mf * 16 + gid]     = sums[mf * 2];
            red[wn][wm * 32 + mf * 16 + 8 + gid] = sums[mf * 2 + 1];
        }
    }
    __syncthreads();
    #pragma unroll
    for (int mf = 0; mf < 2; mf++) {
        const int lr0 = wm * 32 + mf * 16 + gid;
        inv[mf * 2]     = 1.0f / (red[0][lr0] + red[1][lr0]);
        inv[mf * 2 + 1] = 1.0f / (red[0][lr0 + 8] + red[1][lr0 + 8]);
    }

    // ---------------- pass 2: recompute, normalize, stream out ----------------
    float* const obase = out + ((size_t)bh * T + t0 + wm * 32 + gid) * T + 2 * tig;

    #define P2_GROUP(va, vb, ci, ntg) {                                       \
        MMA_GROUP(va, vb)                                                     \
        float* pp = obase + (ci) * 64 + (ntg) * 8;                            \
        *(float2*)pp            = make_float2(ex2(c0[0]) * inv[0], ex2(c0[1]) * inv[0]); \
        *(float2*)(pp + 8 * T)  = make_float2(ex2(c0[2]) * inv[1], ex2(c0[3]) * inv[1]); \
        *(float2*)(pp + 16 * T) = make_float2(ex2(c1[0]) * inv[2], ex2(c1[1]) * inv[2]); \
        *(float2*)(pp + 24 * T) = make_float2(ex2(c1[2]) * inv[3], ex2(c1[3]) * inv[3]); }

    for (int ci = 0; ci < 25; ci++) {
        { P2_GROUP(kb[0][0], kb[0][1], ci, wn * 4) }
        { P2_GROUP(kb[0][2], kb[0][3], ci, wn * 4 + 1) }
        if (ci < 24) LOADP(0, ci + 1, 0)
        { P2_GROUP(kb[1][0], kb[1][1], ci, wn * 4 + 2) }
        { P2_GROUP(kb[1][2], kb[1][3], ci, wn * 4 + 3) }
        if (ci < 24) LOADP(1, ci + 1, 1)
    }

    #undef LOADP
    #undef MMA_GROUP
    #undef P1_GROUP
    #undef P2_GROUP
}

extern "C" void kernel_launch(void* const* d_in, const int* in_sizes, int n_in,
                              void* d_out, int out_size)
{
    (void)in_sizes; (void)n_in; (void)out_size;
    const float* feat  = (const float*)d_in[0];
    const float* ln_w  = (const float*)d_in[1];
    const float* ln_b  = (const float*)d_in[2];
    const float* qkv_w = (const float*)d_in[3];
    const float* qkv_b = (const float*)d_in[4];
    float* out = (float*)d_out;

    cudaFuncSetAttribute(ln_qkv_kernel, cudaFuncAttributeMaxDynamicSharedMemorySize,
                         K1_SMEM_FLOATS * 4);

    ln_qkv_kernel<<<dim3(4, 200), 256, K1_SMEM_FLOATS * 4>>>(feat, ln_w, ln_b, qkv_w, qkv_b);
    attn_kernel<<<dim3(25, 64), 128>>>(out);
}

// round 9
// speedup vs baseline: 1.0873x; 1.0133x over previous
#include <cuda_runtime.h>

#define T 1600
#define BH 64
#define HD 32
// softmax scale * log2(e): scores are computed in exp2 domain
#define QSCALE (0.17677669529663687f * 1.4426950408889634f)

// Pre-fragmented Q/K scratch (tf32-rounded fp32), written by kernel 1 in mma
// fragment order so kernel 2 loads fragments with coalesced LDG.128.
// Qf: [bh][rt=t/16][kk=d/8][lane][reg]   reg = ((d>>2)&1)*2 + ((t>>3)&1)
// Kf: [bh][si=t/64][nt=(t/8)%8][v=kk/2][lane][(kk&1)*2+b]
//     -> one nt-group = 2 vecs x 32 lanes x float4; lane stride 16B (coalesced)
static __device__ float g_Qf[(size_t)BH * 100 * 4 * 32 * 4];
static __device__ float g_Kf[(size_t)BH * 25 * 8 * 2 * 32 * 4];

__device__ __forceinline__ unsigned f2tf32(float f) {
    unsigned r;
    asm("cvt.rna.tf32.f32 %0, %1;" : "=r"(r) : "f"(f));
    return r;
}

__device__ __forceinline__ float ex2(float x) {
    float y;
    asm("ex2.approx.ftz.f32 %0, %1;" : "=f"(y) : "f"(x));
    return y;
}

__device__ __forceinline__ void mma_tf32(float c[4], const unsigned a[4], const unsigned b[2]) {
    asm volatile(
        "mma.sync.aligned.m16n8k8.row.col.f32.tf32.tf32.f32 "
        "{%0,%1,%2,%3}, {%4,%5,%6,%7}, {%8,%9}, {%0,%1,%2,%3};\n"
        : "+f"(c[0]), "+f"(c[1]), "+f"(c[2]), "+f"(c[3])
        : "r"(a[0]), "r"(a[1]), "r"(a[2]), "r"(a[3]), "r"(b[0]), "r"(b[1]));
}

__device__ __forceinline__ void store_qfrag(int bh, int t, int d, float v) {
    const int rt = t >> 4, gid = t & 7, rlo = (t >> 3) & 1;
    const int kk = d >> 3, tig = d & 3, rhi = (d >> 2) & 1;
    g_Qf[((((size_t)bh * 100 + rt) * 4 + kk) * 32 + gid * 4 + tig) * 4 + rhi * 2 + rlo] = v;
}

__device__ __forceinline__ void store_kfrag(int bh, int t, int d, float v) {
    const int si = t >> 6, nt = (t >> 3) & 7, gid = t & 7;
    const int kk = d >> 3, tig = d & 3, b = (d >> 2) & 1;
    g_Kf[(((size_t)bh * 25 + si) * 8 + nt) * 256
         + (kk >> 1) * 128 + (gid * 4 + tig) * 4 + (kk & 1) * 2 + b] = v;
}

// ===================== Kernel 1: LayerNorm + QKV projection (Q,K only) =====================
#define XS_STRIDE 72
#define WS_STRIDE 68
#define K1_SMEM_FLOATS (256 * XS_STRIDE + 128 * WS_STRIDE + 256 + 256 + 64 + 64)

__global__ void __launch_bounds__(256) ln_qkv_kernel(
    const float* __restrict__ feat, const float* __restrict__ ln_w,
    const float* __restrict__ ln_b, const float* __restrict__ qkv_w,
    const float* __restrict__ qkv_b)
{
    extern __shared__ float sm[];
    float* xs  = sm;                        // [256][72] raw x, [c][t]
    float* ws  = xs + 256 * XS_STRIDE;      // [128][68] tf32 W chunk, [n][c]
    float* lw  = ws + 128 * WS_STRIDE;      // [256]
    float* lb  = lw + 256;                  // [256]
    float* mus = lb + 256;                  // [64]
    float* rss = mus + 64;                  // [64]

    const int tid = threadIdx.x;
    const int n0 = blockIdx.x * 128;        // 0,128 -> Q ; 256,384 -> K
    const int tb = blockIdx.y;              // 0..199
    const int b  = tb / 25;
    const int t0 = (tb % 25) * 64;

    {
        const float* src = feat + ((size_t)b * 256) * T + t0;
        const int c4 = (tid & 15) * 4;
        #pragma unroll 4
        for (int c = tid >> 4; c < 256; c += 16) {
            const float4 v = *(const float4*)(src + (size_t)c * T + c4);
            float* d = xs + c * XS_STRIDE + c4;
            d[0] = v.x; d[1] = v.y; d[2] = v.z; d[3] = v.w;
        }
        lw[tid] = ln_w[tid];
        lb[tid] = ln_b[tid];
    }
    __syncthreads();

    {
        const int t = tid >> 2, g = tid & 3;
        float s = 0.f, sq = 0.f;
        for (int c = g; c < 256; c += 4) {
            const float v = xs[c * XS_STRIDE + t];
            s += v; sq += v * v;
        }
        s += __shfl_xor_sync(~0u, s, 1); sq += __shfl_xor_sync(~0u, sq, 1);
        s += __shfl_xor_sync(~0u, s, 2); sq += __shfl_xor_sync(~0u, sq, 2);
        if (g == 0) {
            const float mu = s * (1.f / 256.f);
            mus[t] = mu;
            rss[t] = rsqrtf(sq * (1.f / 256.f) - mu * mu + 1e-6f);
        }
    }
    __syncthreads();

    const int warp = tid >> 5, lane = tid & 31;
    const int wm = warp >> 1, wn = warp & 1;
    const int gid = lane >> 2, tig = lane & 3;
    const int tl = wm * 16 + gid;
    const float mu0 = mus[tl], rs0 = rss[tl], mu1 = mus[tl + 8], rs1 = rss[tl + 8];

    float acc[8][4];
    #pragma unroll
    for (int i = 0; i < 8; i++) {
        #pragma unroll
        for (int j = 0; j < 4; j++) acc[i][j] = 0.f;
    }

    for (int kc = 0; kc < 4; kc++) {
        const int c0 = kc * 64;
        __syncthreads();
        {
            const int c4 = (tid & 15) * 4;
            const float* wsrc = qkv_w + (size_t)n0 * 256 + c0 + c4;
            #pragma unroll
            for (int n = tid >> 4; n < 128; n += 16) {
                const float4 v = *(const float4*)(wsrc + (size_t)n * 256);
                float* d = ws + n * WS_STRIDE + c4;
                d[0] = __uint_as_float(f2tf32(v.x));
                d[1] = __uint_as_float(f2tf32(v.y));
                d[2] = __uint_as_float(f2tf32(v.z));
                d[3] = __uint_as_float(f2tf32(v.w));
            }
        }
        __syncthreads();
        #pragma unroll
        for (int kk = 0; kk < 8; kk++) {
            const int c = c0 + kk * 8 + tig;
            const float wc = lw[c], bc = lb[c], wc4 = lw[c + 4], bc4 = lb[c + 4];
            unsigned a[4];
            a[0] = f2tf32((xs[c * XS_STRIDE + tl]           - mu0) * rs0 * wc  + bc);
            a[1] = f2tf32((xs[c * XS_STRIDE + tl + 8]       - mu1) * rs1 * wc  + bc);
            a[2] = f2tf32((xs[(c + 4) * XS_STRIDE + tl]     - mu0) * rs0 * wc4 + bc4);
            a[3] = f2tf32((xs[(c + 4) * XS_STRIDE + tl + 8] - mu1) * rs1 * wc4 + bc4);
            #pragma unroll
            for (int nt = 0; nt < 8; nt++) {
                const int nl = wn * 64 + nt * 8 + gid;
                unsigned bf[2];
                bf[0] = __float_as_uint(ws[nl * WS_STRIDE + kk * 8 + tig]);
                bf[1] = __float_as_uint(ws[nl * WS_STRIDE + kk * 8 + tig + 4]);
                mma_tf32(acc[nt], a, bf);
            }
        }
    }

    const bool is_q = (n0 < 256);
    const int trow = t0 + tl;
    #pragma unroll
    for (int nt = 0; nt < 8; nt++) {
        const int ng = n0 + wn * 64 + nt * 8 + 2 * tig;
        const int nq = is_q ? ng : (ng - 256);
        const int h = nq >> 5, d = nq & 31;
        const int bh = b * 8 + h;
        const float bias0 = qkv_b[ng], bias1 = qkv_b[ng + 1];
        float v0 = acc[nt][0] + bias0, v1 = acc[nt][1] + bias1;
        float v2 = acc[nt][2] + bias0, v3 = acc[nt][3] + bias1;
        if (is_q) {
            v0 *= QSCALE; v1 *= QSCALE; v2 *= QSCALE; v3 *= QSCALE;
            store_qfrag(bh, trow,     d,     __uint_as_float(f2tf32(v0)));
            store_qfrag(bh, trow,     d + 1, __uint_as_float(f2tf32(v1)));
            store_qfrag(bh, trow + 8, d,     __uint_as_float(f2tf32(v2)));
            store_qfrag(bh, trow + 8, d + 1, __uint_as_float(f2tf32(v3)));
        } else {
            store_kfrag(bh, trow,     d,     __uint_as_float(f2tf32(v0)));
            store_kfrag(bh, trow,     d + 1, __uint_as_float(f2tf32(v1)));
            store_kfrag(bh, trow + 8, d,     __uint_as_float(f2tf32(v2)));
            store_kfrag(bh, trow + 8, d + 1, __uint_as_float(f2tf32(v3)));
        }
    }
}

// ===================== Kernel 2: direct-LDG K, half-chunk register pipeline ======
// r6 structure: 128 thr / 4 warps, 2x2 split; wm -> 32 rows (2 m-frags),
// wn -> 32 of 64 chunk cols. K fragments LDG'd straight from fragment-ordered
// gmem into a 2 x 4-float4 register double buffer at HALF-CHUNK granularity.
// New Kf interleave: lane stride 16B -> every load is a fully-coalesced LDG.128
// (512B/warp/instr). 4 independent LDG.128 in flight, one half-chunk of cover.
__global__ void __launch_bounds__(128, 5) attn_kernel(float* __restrict__ out)
{
    __shared__ float red[2][64];

    const int tid = threadIdx.x;
    const int warp = tid >> 5, lane = tid & 31;
    const int gid = lane >> 2, tig = lane & 3;
    const int wm = warp >> 1, wn = warp & 1;
    const int bh = blockIdx.y;
    const int t0 = blockIdx.x * 64;

    // A fragments: 2 m-frags (32 rows), constant for whole kernel (8x LDG.128)
    unsigned afr[2][4][4];
    #pragma unroll
    for (int mf = 0; mf < 2; mf++) {
        const int rt = blockIdx.x * 4 + wm * 2 + mf;
        const float4* qf = (const float4*)g_Qf + ((size_t)bh * 100 + rt) * 4 * 32 + lane;
        #pragma unroll
        for (int kk = 0; kk < 4; kk++) {
            const float4 v = qf[kk * 32];
            afr[mf][kk][0] = __float_as_uint(v.x);
            afr[mf][kk][1] = __float_as_uint(v.y);
            afr[mf][kk][2] = __float_as_uint(v.z);
            afr[mf][kk][3] = __float_as_uint(v.w);
        }
    }

    // per-thread K fragment base; chunk = 512 float4, nt-group = 64 float4
    const float4* kw = (const float4*)g_Kf + (size_t)bh * 25 * 512 + lane;

    float4 kb[2][4];      // [buf][group*2 + vec]
    float sums[4] = {0.f, 0.f, 0.f, 0.f};
    float inv[4];

    // load half-chunk p (nt groups wn*4+2p, wn*4+2p+1) of chunk si into kb[buf]
    // 4 fully-coalesced LDG.128 (offsets 0,32,64,96 float4 from group base)
    #define LOADP(buf, si, p) {                                               \
        const float4* p_ = kw + (size_t)(si) * 512 + (wn * 4 + (p) * 2) * 64; \
        kb[buf][0] = p_[0];  kb[buf][1] = p_[32];                             \
        kb[buf][2] = p_[64]; kb[buf][3] = p_[96]; }

    // compute one 8-col group from two float4s; c0 (rows wm*32..+15), c1 (+16..31)
    #define MMA_GROUP(va, vb)                                                 \
        unsigned bfr[4][2];                                                   \
        bfr[0][0] = __float_as_uint((va).x); bfr[0][1] = __float_as_uint((va).y); \
        bfr[1][0] = __float_as_uint((va).z); bfr[1][1] = __float_as_uint((va).w); \
        bfr[2][0] = __float_as_uint((vb).x); bfr[2][1] = __float_as_uint((vb).y); \
        bfr[3][0] = __float_as_uint((vb).z); bfr[3][1] = __float_as_uint((vb).w); \
        float c0[4] = {0.f,0.f,0.f,0.f}, c1[4] = {0.f,0.f,0.f,0.f};           \
        _Pragma("unroll")                                                     \
        for (int kk = 0; kk < 4; kk++) mma_tf32(c0, afr[0][kk], bfr[kk]);     \
        _Pragma("unroll")                                                     \
        for (int kk = 0; kk < 4; kk++) mma_tf32(c1, afr[1][kk], bfr[kk]);

    // ---------------- pass 1: row sums of exp2(scores) ----------------
    #define P1_GROUP(va, vb) {                                                \
        MMA_GROUP(va, vb)                                                     \
        sums[0] += ex2(c0[0]) + ex2(c0[1]);                                   \
        sums[1] += ex2(c0[2]) + ex2(c0[3]);                                   \
        sums[2] += ex2(c1[0]) + ex2(c1[1]);                                   \
        sums[3] += ex2(c1[2]) + ex2(c1[3]); }

    LOADP(0, 0, 0)
    LOADP(1, 0, 1)
    for (int ci = 0; ci < 25; ci++) {
        const int nsi = (ci == 24) ? 0 : ci + 1;   // wrap: prefetch chunk 0 for pass 2
        { P1_GROUP(kb[0][0], kb[0][1]) }
        { P1_GROUP(kb[0][2], kb[0][3]) }
        LOADP(0, nsi, 0)
        { P1_GROUP(kb[1][0], kb[1][1]) }
        { P1_GROUP(kb[1][2], kb[1][3]) }
        LOADP(1, nsi, 1)
    }

    // ---------------- cross-warp row-sum reduction ----------------
    #pragma unroll
    for (int i = 0; i < 4; i++) {
        sums[i] += __shfl_xor_sync(~0u, sums[i], 1);
        sums[i] += __shfl_xor_sync(~0u, sums[i], 2);
    }
    if (tig == 0) {
        #pragma unroll
        for (int mf = 0; mf < 2; mf++) {
            red[wn][wm * 32 + mf * 16 + gid]     = sums[mf * 2];
            red[wn][wm * 32 + mf * 16 + 8 + gid] = sums[mf * 2 + 1];
        }
    }
    __syncthreads();
    #pragma unroll
    for (int mf = 0; mf < 2; mf++) {
        const int lr0 = wm * 32 + mf * 16 + gid;
        inv[mf * 2]     = 1.0f / (red[0][lr0] + red[1][lr0]);
        inv[mf * 2 + 1] = 1.0f / (red[0][lr0 + 8] + red[1][lr0 + 8]);
    }

    // ---------------- pass 2: recompute, normalize, stream out ----------------
    float* const obase = out + ((size_t)bh * T + t0 + wm * 32 + gid) * T + 2 * tig;

    #define P2_GROUP(va, vb, ci, ntg) {                                       \
        MMA_GROUP(va, vb)                                                     \
        float* pp = obase + (ci) * 64 + (ntg) * 8;                            \
        *(float2*)pp            = make_float2(ex2(c0[0]) * inv[0], ex2(c0[1]) * inv[0]); \
        *(float2*)(pp + 8 * T)  = make_float2(ex2(c0[2]) * inv[1], ex2(c0[3]) * inv[1]); \
        *(float2*)(pp + 16 * T) = make_float2(ex2(c1[0]) * inv[2], ex2(c1[1]) * inv[2]); \
        *(float2*)(pp + 24 * T) = make_float2(ex2(c1[2]) * inv[3], ex2(c1[3]) * inv[3]); }

    for (int ci = 0; ci < 25; ci++) {
        { P2_GROUP(kb[0][0], kb[0][1], ci, wn * 4) }
        { P2_GROUP(kb[0][2], kb[0][3], ci, wn * 4 + 1) }
        if (ci < 24) LOADP(0, ci + 1, 0)
        { P2_GROUP(kb[1][0], kb[1][1], ci, wn * 4 + 2) }
        { P2_GROUP(kb[1][2], kb[1][3], ci, wn * 4 + 3) }
        if (ci < 24) LOADP(1, ci + 1, 1)
    }

    #undef LOADP
    #undef MMA_GROUP
    #undef P1_GROUP
    #undef P2_GROUP
}

extern "C" void kernel_launch(void* const* d_in, const int* in_sizes, int n_in,
                              void* d_out, int out_size)
{
    (void)in_sizes; (void)n_in; (void)out_size;
    const float* feat  = (const float*)d_in[0];
    const float* ln_w  = (const float*)d_in[1];
    const float* ln_b  = (const float*)d_in[2];
    const float* qkv_w = (const float*)d_in[3];
    const float* qkv_b = (const float*)d_in[4];
    float* out = (float*)d_out;

    cudaFuncSetAttribute(ln_qkv_kernel, cudaFuncAttributeMaxDynamicSharedMemorySize,
                         K1_SMEM_FLOATS * 4);

    ln_qkv_kernel<<<dim3(4, 200), 256, K1_SMEM_FLOATS * 4>>>(feat, ln_w, ln_b, qkv_w, qkv_b);
    attn_kernel<<<dim3(25, 64), 128>>>(out);
}

// round 10
// speedup vs baseline: 1.2541x; 1.1534x over previous
#include <cuda_runtime.h>

#define T 1600
#define BH 64
#define HD 32
// softmax scale * log2(e): scores are computed in exp2 domain
#define QSCALE (0.17677669529663687f * 1.4426950408889634f)

// Pre-fragmented Q/K scratch (tf32-rounded fp32), written by kernel 1 in mma
// fragment order so kernel 2 loads fragments with coalesced LDG.128 / cp.async.
// Qf: [bh][rt=t/16][kk=d/8][lane][reg]   reg = ((d>>2)&1)*2 + ((t>>3)&1)
// Kf: [bh][si=t/64][nt=(t/8)%8][v=kk/2][lane][(kk&1)*2+b]
static __device__ float g_Qf[(size_t)BH * 100 * 4 * 32 * 4];
static __device__ float g_Kf[(size_t)BH * 25 * 8 * 2 * 32 * 4];

__device__ __forceinline__ unsigned f2tf32(float f) {
    unsigned r;
    asm("cvt.rna.tf32.f32 %0, %1;" : "=r"(r) : "f"(f));
    return r;
}

__device__ __forceinline__ float ex2(float x) {
    float y;
    asm("ex2.approx.ftz.f32 %0, %1;" : "=f"(y) : "f"(x));
    return y;
}

__device__ __forceinline__ void mma_tf32(float c[4], const unsigned a[4], const unsigned b[2]) {
    asm volatile(
        "mma.sync.aligned.m16n8k8.row.col.f32.tf32.tf32.f32 "
        "{%0,%1,%2,%3}, {%4,%5,%6,%7}, {%8,%9}, {%0,%1,%2,%3};\n"
        : "+f"(c[0]), "+f"(c[1]), "+f"(c[2]), "+f"(c[3])
        : "r"(a[0]), "r"(a[1]), "r"(a[2]), "r"(a[3]), "r"(b[0]), "r"(b[1]));
}

__device__ __forceinline__ void cp_async16(unsigned smem_addr, const void* gptr) {
    asm volatile("cp.async.cg.shared.global [%0], [%1], 16;"
                 :: "r"(smem_addr), "l"(gptr));
}

__device__ __forceinline__ void store_qfrag(int bh, int t, int d, float v) {
    const int rt = t >> 4, gid = t & 7, rlo = (t >> 3) & 1;
    const int kk = d >> 3, tig = d & 3, rhi = (d >> 2) & 1;
    g_Qf[((((size_t)bh * 100 + rt) * 4 + kk) * 32 + gid * 4 + tig) * 4 + rhi * 2 + rlo] = v;
}

__device__ __forceinline__ void store_kfrag(int bh, int t, int d, float v) {
    const int si = t >> 6, nt = (t >> 3) & 7, gid = t & 7;
    const int kk = d >> 3, tig = d & 3, b = (d >> 2) & 1;
    g_Kf[(((size_t)bh * 25 + si) * 8 + nt) * 256
         + (kk >> 1) * 128 + (gid * 4 + tig) * 4 + (kk & 1) * 2 + b] = v;
}

// ===================== Kernel 1: LayerNorm + QKV projection (Q,K only) =====================
#define XS_STRIDE 72
#define WS_STRIDE 68
#define K1_SMEM_FLOATS (256 * XS_STRIDE + 128 * WS_STRIDE + 256 + 256 + 64 + 64)

__global__ void __launch_bounds__(256) ln_qkv_kernel(
    const float* __restrict__ feat, const float* __restrict__ ln_w,
    const float* __restrict__ ln_b, const float* __restrict__ qkv_w,
    const float* __restrict__ qkv_b)
{
    extern __shared__ float sm[];
    float* xs  = sm;                        // [256][72] raw x, [c][t]
    float* ws  = xs + 256 * XS_STRIDE;      // [128][68] tf32 W chunk, [n][c]
    float* lw  = ws + 128 * WS_STRIDE;      // [256]
    float* lb  = lw + 256;                  // [256]
    float* mus = lb + 256;                  // [64]
    float* rss = mus + 64;                  // [64]

    const int tid = threadIdx.x;
    const int n0 = blockIdx.x * 128;        // 0,128 -> Q ; 256,384 -> K
    const int tb = blockIdx.y;              // 0..199
    const int b  = tb / 25;
    const int t0 = (tb % 25) * 64;

    {
        const float* src = feat + ((size_t)b * 256) * T + t0;
        const int c4 = (tid & 15) * 4;
        #pragma unroll 4
        for (int c = tid >> 4; c < 256; c += 16) {
            const float4 v = *(const float4*)(src + (size_t)c * T + c4);
            float* d = xs + c * XS_STRIDE + c4;
            d[0] = v.x; d[1] = v.y; d[2] = v.z; d[3] = v.w;
        }
        lw[tid] = ln_w[tid];
        lb[tid] = ln_b[tid];
    }
    __syncthreads();

    {
        const int t = tid >> 2, g = tid & 3;
        float s = 0.f, sq = 0.f;
        for (int c = g; c < 256; c += 4) {
            const float v = xs[c * XS_STRIDE + t];
            s += v; sq += v * v;
        }
        s += __shfl_xor_sync(~0u, s, 1); sq += __shfl_xor_sync(~0u, sq, 1);
        s += __shfl_xor_sync(~0u, s, 2); sq += __shfl_xor_sync(~0u, sq, 2);
        if (g == 0) {
            const float mu = s * (1.f / 256.f);
            mus[t] = mu;
            rss[t] = rsqrtf(sq * (1.f / 256.f) - mu * mu + 1e-6f);
        }
    }
    __syncthreads();

    const int warp = tid >> 5, lane = tid & 31;
    const int wm = warp >> 1, wn = warp & 1;
    const int gid = lane >> 2, tig = lane & 3;
    const int tl = wm * 16 + gid;
    const float mu0 = mus[tl], rs0 = rss[tl], mu1 = mus[tl + 8], rs1 = rss[tl + 8];

    float acc[8][4];
    #pragma unroll
    for (int i = 0; i < 8; i++) {
        #pragma unroll
        for (int j = 0; j < 4; j++) acc[i][j] = 0.f;
    }

    for (int kc = 0; kc < 4; kc++) {
        const int c0 = kc * 64;
        __syncthreads();
        {
            const int c4 = (tid & 15) * 4;
            const float* wsrc = qkv_w + (size_t)n0 * 256 + c0 + c4;
            #pragma unroll
            for (int n = tid >> 4; n < 128; n += 16) {
                const float4 v = *(const float4*)(wsrc + (size_t)n * 256);
                float* d = ws + n * WS_STRIDE + c4;
                d[0] = __uint_as_float(f2tf32(v.x));
                d[1] = __uint_as_float(f2tf32(v.y));
                d[2] = __uint_as_float(f2tf32(v.z));
                d[3] = __uint_as_float(f2tf32(v.w));
            }
        }
        __syncthreads();
        #pragma unroll
        for (int kk = 0; kk < 8; kk++) {
            const int c = c0 + kk * 8 + tig;
            const float wc = lw[c], bc = lb[c], wc4 = lw[c + 4], bc4 = lb[c + 4];
            unsigned a[4];
            a[0] = f2tf32((xs[c * XS_STRIDE + tl]           - mu0) * rs0 * wc  + bc);
            a[1] = f2tf32((xs[c * XS_STRIDE + tl + 8]       - mu1) * rs1 * wc  + bc);
            a[2] = f2tf32((xs[(c + 4) * XS_STRIDE + tl]     - mu0) * rs0 * wc4 + bc4);
            a[3] = f2tf32((xs[(c + 4) * XS_STRIDE + tl + 8] - mu1) * rs1 * wc4 + bc4);
            #pragma unroll
            for (int nt = 0; nt < 8; nt++) {
                const int nl = wn * 64 + nt * 8 + gid;
                unsigned bf[2];
                bf[0] = __float_as_uint(ws[nl * WS_STRIDE + kk * 8 + tig]);
                bf[1] = __float_as_uint(ws[nl * WS_STRIDE + kk * 8 + tig + 4]);
                mma_tf32(acc[nt], a, bf);
            }
        }
    }

    const bool is_q = (n0 < 256);
    const int trow = t0 + tl;
    #pragma unroll
    for (int nt = 0; nt < 8; nt++) {
        const int ng = n0 + wn * 64 + nt * 8 + 2 * tig;
        const int nq = is_q ? ng : (ng - 256);
        const int h = nq >> 5, d = nq & 31;
        const int bh = b * 8 + h;
        const float bias0 = qkv_b[ng], bias1 = qkv_b[ng + 1];
        float v0 = acc[nt][0] + bias0, v1 = acc[nt][1] + bias1;
        float v2 = acc[nt][2] + bias0, v3 = acc[nt][3] + bias1;
        if (is_q) {
            v0 *= QSCALE; v1 *= QSCALE; v2 *= QSCALE; v3 *= QSCALE;
            store_qfrag(bh, trow,     d,     __uint_as_float(f2tf32(v0)));
            store_qfrag(bh, trow,     d + 1, __uint_as_float(f2tf32(v1)));
            store_qfrag(bh, trow + 8, d,     __uint_as_float(f2tf32(v2)));
            store_qfrag(bh, trow + 8, d + 1, __uint_as_float(f2tf32(v3)));
        } else {
            store_kfrag(bh, trow,     d,     __uint_as_float(f2tf32(v0)));
            store_kfrag(bh, trow,     d + 1, __uint_as_float(f2tf32(v1)));
            store_kfrag(bh, trow + 8, d,     __uint_as_float(f2tf32(v2)));
            store_kfrag(bh, trow + 8, d + 1, __uint_as_float(f2tf32(v3)));
        }
    }
}

// ===================== Kernel 2: cp.async 4-stage smem pipeline attention ========
// 128 thr / 4 warps, 2x2 split: wm -> 32 rows (2 m-frags), wn -> 32 of 64 chunk
// cols. K chunks flow gmem -> smem via cp.async.cg (no register staging), 4
// stages x 8KB, 3 chunks of prefetch depth (>900 cyc cover vs ~260 L2 latency).
// B fragments read from smem with conflict-free LDS.128 (lane stride 16B).
// Single 50-iter loop: gi<25 = pass 1 (row sums of exp2), gi>=25 = pass 2
// (recompute + normalized store). Row-sum reduction inline at gi==24 while
// prefetches stay in flight.
#define NSTAGE 4

__global__ void __launch_bounds__(128, 6) attn_kernel(float* __restrict__ out)
{
    __shared__ float4 Ks[NSTAGE][512];     // 4 x 8KB chunk stages
    __shared__ float red[2][64];

    const int tid = threadIdx.x;
    const int warp = tid >> 5, lane = tid & 31;
    const int gid = lane >> 2, tig = lane & 3;
    const int wm = warp >> 1, wn = warp & 1;
    const int bh = blockIdx.y;
    const int t0 = blockIdx.x * 64;

    // A fragments: 2 m-frags (32 rows), constant for whole kernel (8x LDG.128)
    unsigned afr[2][4][4];
    #pragma unroll
    for (int mf = 0; mf < 2; mf++) {
        const int rt = blockIdx.x * 4 + wm * 2 + mf;
        const float4* qf = (const float4*)g_Qf + ((size_t)bh * 100 + rt) * 4 * 32 + lane;
        #pragma unroll
        for (int kk = 0; kk < 4; kk++) {
            const float4 v = qf[kk * 32];
            afr[mf][kk][0] = __float_as_uint(v.x);
            afr[mf][kk][1] = __float_as_uint(v.y);
            afr[mf][kk][2] = __float_as_uint(v.z);
            afr[mf][kk][3] = __float_as_uint(v.w);
        }
    }

    const float4* ksrc = (const float4*)g_Kf + (size_t)bh * 25 * 512;
    const unsigned ks_u32 = (unsigned)__cvta_generic_to_shared(&Ks[0][0]) + tid * 16;

    // prefetch chunk c into stage s: 4 coalesced 16B cp.async per thread (8KB/CTA)
    #define PREFETCH(c, s) {                                                  \
        const unsigned d_ = ks_u32 + (s) * 8192;                              \
        const float4* s_ = ksrc + (size_t)(c) * 512 + tid;                    \
        cp_async16(d_,        s_);                                            \
        cp_async16(d_ + 2048, s_ + 128);                                      \
        cp_async16(d_ + 4096, s_ + 256);                                      \
        cp_async16(d_ + 6144, s_ + 384);                                      \
        asm volatile("cp.async.commit_group;"); }

    #define MMA_GROUP(va, vb)                                                 \
        unsigned bfr[4][2];                                                   \
        bfr[0][0] = __float_as_uint((va).x); bfr[0][1] = __float_as_uint((va).y); \
        bfr[1][0] = __float_as_uint((va).z); bfr[1][1] = __float_as_uint((va).w); \
        bfr[2][0] = __float_as_uint((vb).x); bfr[2][1] = __float_as_uint((vb).y); \
        bfr[3][0] = __float_as_uint((vb).z); bfr[3][1] = __float_as_uint((vb).w); \
        float c0[4] = {0.f,0.f,0.f,0.f}, c1[4] = {0.f,0.f,0.f,0.f};           \
        _Pragma("unroll")                                                     \
        for (int kk = 0; kk < 4; kk++) mma_tf32(c0, afr[0][kk], bfr[kk]);     \
        _Pragma("unroll")                                                     \
        for (int kk = 0; kk < 4; kk++) mma_tf32(c1, afr[1][kk], bfr[kk]);

    float sums[4] = {0.f, 0.f, 0.f, 0.f};
    float inv[4];
    float* const obase = out + ((size_t)bh * T + t0 + wm * 32 + gid) * T + 2 * tig;

    // prime 3 stages
    PREFETCH(0, 0)
    PREFETCH(1, 1)
    PREFETCH(2, 2)

    for (int gi = 0; gi < 50; gi++) {
        asm volatile("cp.async.wait_group 2;");
        __syncthreads();                       // chunk gi ready; stage (gi-1)&3 consumed by all
        {   // prefetch chunk gi+3 (wraps; tail wraps are harmless reloads)
            const int c3 = gi + 3;
            const int ch = (c3 >= 50) ? (c3 - 50) : (c3 >= 25 ? c3 - 25 : c3);
            PREFETCH(ch, c3 & 3)
        }
        const float4* kb = Ks[gi & 3];
        if (gi < 25) {
            #pragma unroll
            for (int g = 0; g < 4; g++) {
                const int ntg = wn * 4 + g;
                const float4 va = kb[ntg * 64 + lane];
                const float4 vb = kb[ntg * 64 + 32 + lane];
                MMA_GROUP(va, vb)
                sums[0] += ex2(c0[0]) + ex2(c0[1]);
                sums[1] += ex2(c0[2]) + ex2(c0[3]);
                sums[2] += ex2(c1[0]) + ex2(c1[1]);
                sums[3] += ex2(c1[2]) + ex2(c1[3]);
            }
            if (gi == 24) {
                // cross-warp row-sum reduction (prefetches remain in flight)
                #pragma unroll
                for (int i = 0; i < 4; i++) {
                    sums[i] += __shfl_xor_sync(~0u, sums[i], 1);
                    sums[i] += __shfl_xor_sync(~0u, sums[i], 2);
                }
                if (tig == 0) {
                    #pragma unroll
                    for (int mf = 0; mf < 2; mf++) {
                        red[wn][wm * 32 + mf * 16 + gid]     = sums[mf * 2];
                        red[wn][wm * 32 + mf * 16 + 8 + gid] = sums[mf * 2 + 1];
                    }
                }
                __syncthreads();
                #pragma unroll
                for (int mf = 0; mf < 2; mf++) {
                    const int lr0 = wm * 32 + mf * 16 + gid;
                    inv[mf * 2]     = 1.0f / (red[0][lr0] + red[1][lr0]);
                    inv[mf * 2 + 1] = 1.0f / (red[0][lr0 + 8] + red[1][lr0 + 8]);
                }
            }
        } else {
            const int ci = gi - 25;
            #pragma unroll
            for (int g = 0; g < 4; g++) {
                const int ntg = wn * 4 + g;
                const float4 va = kb[ntg * 64 + lane];
                const float4 vb = kb[ntg * 64 + 32 + lane];
                MMA_GROUP(va, vb)
                float* pp = obase + ci * 64 + ntg * 8;
                *(float2*)pp            = make_float2(ex2(c0[0]) * inv[0], ex2(c0[1]) * inv[0]);
                *(float2*)(pp + 8 * T)  = make_float2(ex2(c0[2]) * inv[1], ex2(c0[3]) * inv[1]);
                *(float2*)(pp + 16 * T) = make_float2(ex2(c1[0]) * inv[2], ex2(c1[1]) * inv[2]);
                *(float2*)(pp + 24 * T) = make_float2(ex2(c1[2]) * inv[3], ex2(c1[3]) * inv[3]);
            }
        }
    }

    #undef PREFETCH
    #undef MMA_GROUP
}

extern "C" void kernel_launch(void* const* d_in, const int* in_sizes, int n_in,
                              void* d_out, int out_size)
{
    (void)in_sizes; (void)n_in; (void)out_size;
    const float* feat  = (const float*)d_in[0];
    const float* ln_w  = (const float*)d_in[1];
    const float* ln_b  = (const float*)d_in[2];
    const float* qkv_w = (const float*)d_in[3];
    const float* qkv_b = (const float*)d_in[4];
    float* out = (float*)d_out;

    cudaFuncSetAttribute(ln_qkv_kernel, cudaFuncAttributeMaxDynamicSharedMemorySize,
                         K1_SMEM_FLOATS * 4);

    ln_qkv_kernel<<<dim3(4, 200), 256, K1_SMEM_FLOATS * 4>>>(feat, ln_w, ln_b, qkv_w, qkv_b);
    attn_kernel<<<dim3(25, 64), 128>>>(out);
}

// round 11
// speedup vs baseline: 1.5462x; 1.2329x over previous
#include <cuda_runtime.h>
#include <cuda_fp16.h>

#define T 1600
#define BH 64
#define HD 32
// softmax scale * log2(e): scores are computed in exp2 domain
#define QSCALE (0.17677669529663687f * 1.4426950408889634f)

// Pre-fragmented Q/K scratch in fp16 mma fragment order (m16n8k16).
// Qf: [bh][rt=t/16][kb=d/16][lane][reg]  reg = colhalf*2 + rowhalf (a0..a3)
// Kf: [bh][si=t/64][nt][lane][reg]       reg = kb*2 + bhalf       (b0,b1 per kb)
static __device__ unsigned g_Qf[(size_t)BH * 100 * 2 * 32 * 4];
static __device__ unsigned g_Kf[(size_t)BH * 25 * 8 * 32 * 4];

__device__ __forceinline__ unsigned f2tf32(float f) {
    unsigned r;
    asm("cvt.rna.tf32.f32 %0, %1;" : "=r"(r) : "f"(f));
    return r;
}

__device__ __forceinline__ unsigned pack_h2(float a, float b) {
    __half2 h = __floats2half2_rn(a, b);   // lo = a (lower k/col index)
    return *(unsigned*)&h;
}

__device__ __forceinline__ float ex2(float x) {
    float y;
    asm("ex2.approx.ftz.f32 %0, %1;" : "=f"(y) : "f"(x));
    return y;
}

// tf32 mma (kernel 1 only)
__device__ __forceinline__ void mma_tf32(float c[4], const unsigned a[4], const unsigned b[2]) {
    asm volatile(
        "mma.sync.aligned.m16n8k8.row.col.f32.tf32.tf32.f32 "
        "{%0,%1,%2,%3}, {%4,%5,%6,%7}, {%8,%9}, {%0,%1,%2,%3};\n"
        : "+f"(c[0]), "+f"(c[1]), "+f"(c[2]), "+f"(c[3])
        : "r"(a[0]), "r"(a[1]), "r"(a[2]), "r"(a[3]), "r"(b[0]), "r"(b[1]));
}

// fp16 mma m16n8k16, fp32 accum (kernel 2)
__device__ __forceinline__ void mma_f16(float c[4], const unsigned a[4], const unsigned b[2]) {
    asm volatile(
        "mma.sync.aligned.m16n8k16.row.col.f32.f16.f16.f32 "
        "{%0,%1,%2,%3}, {%4,%5,%6,%7}, {%8,%9}, {%0,%1,%2,%3};\n"
        : "+f"(c[0]), "+f"(c[1]), "+f"(c[2]), "+f"(c[3])
        : "r"(a[0]), "r"(a[1]), "r"(a[2]), "r"(a[3]), "r"(b[0]), "r"(b[1]));
}

__device__ __forceinline__ void cp_async16(unsigned smem_addr, const void* gptr) {
    asm volatile("cp.async.cg.shared.global [%0], [%1], 16;"
                 :: "r"(smem_addr), "l"(gptr));
}

// store half2 (dims d, d+1; d even) of Q row t
__device__ __forceinline__ void store_qfrag_h2(int bh, int t, int d, unsigned h2) {
    const int rt = t >> 4, gid = t & 7, rhalf = (t >> 3) & 1;
    const int kb = d >> 4, dd = d & 15;
    const int colhalf = dd >> 3, tig = (dd & 7) >> 1;
    g_Qf[(((size_t)bh * 100 + rt) * 2 + kb) * 128 + (gid * 4 + tig) * 4 + colhalf * 2 + rhalf] = h2;
}

// store half2 (dims d, d+1) of K row (token) t
__device__ __forceinline__ void store_kfrag_h2(int bh, int t, int d, unsigned h2) {
    const int si = t >> 6, nt = (t >> 3) & 7, gid = t & 7;
    const int kb = d >> 4, dd = d & 15;
    const int bhalf = dd >> 3, tig = (dd & 7) >> 1;
    g_Kf[((((size_t)bh * 25 + si) * 8 + nt) * 32 + gid * 4 + tig) * 4 + kb * 2 + bhalf] = h2;
}

// ===================== Kernel 1: LayerNorm + QKV projection (Q,K only) =====================
#define XS_STRIDE 72
#define WS_STRIDE 68
#define K1_SMEM_FLOATS (256 * XS_STRIDE + 128 * WS_STRIDE + 256 + 256 + 64 + 64)

__global__ void __launch_bounds__(256) ln_qkv_kernel(
    const float* __restrict__ feat, const float* __restrict__ ln_w,
    const float* __restrict__ ln_b, const float* __restrict__ qkv_w,
    const float* __restrict__ qkv_b)
{
    extern __shared__ float sm[];
    float* xs  = sm;                        // [256][72] raw x, [c][t]
    float* ws  = xs + 256 * XS_STRIDE;      // [128][68] tf32 W chunk, [n][c]
    float* lw  = ws + 128 * WS_STRIDE;      // [256]
    float* lb  = lw + 256;                  // [256]
    float* mus = lb + 256;                  // [64]
    float* rss = mus + 64;                  // [64]

    const int tid = threadIdx.x;
    const int n0 = blockIdx.x * 128;        // 0,128 -> Q ; 256,384 -> K
    const int tb = blockIdx.y;              // 0..199
    const int b  = tb / 25;
    const int t0 = (tb % 25) * 64;

    {
        const float* src = feat + ((size_t)b * 256) * T + t0;
        const int c4 = (tid & 15) * 4;
        #pragma unroll 4
        for (int c = tid >> 4; c < 256; c += 16) {
            const float4 v = *(const float4*)(src + (size_t)c * T + c4);
            float* d = xs + c * XS_STRIDE + c4;
            d[0] = v.x; d[1] = v.y; d[2] = v.z; d[3] = v.w;
        }
        lw[tid] = ln_w[tid];
        lb[tid] = ln_b[tid];
    }
    __syncthreads();

    {
        const int t = tid >> 2, g = tid & 3;
        float s = 0.f, sq = 0.f;
        for (int c = g; c < 256; c += 4) {
            const float v = xs[c * XS_STRIDE + t];
            s += v; sq += v * v;
        }
        s += __shfl_xor_sync(~0u, s, 1); sq += __shfl_xor_sync(~0u, sq, 1);
        s += __shfl_xor_sync(~0u, s, 2); sq += __shfl_xor_sync(~0u, sq, 2);
        if (g == 0) {
            const float mu = s * (1.f / 256.f);
            mus[t] = mu;
            rss[t] = rsqrtf(sq * (1.f / 256.f) - mu * mu + 1e-6f);
        }
    }
    __syncthreads();

    const int warp = tid >> 5, lane = tid & 31;
    const int wm = warp >> 1, wn = warp & 1;
    const int gid = lane >> 2, tig = lane & 3;
    const int tl = wm * 16 + gid;
    const float mu0 = mus[tl], rs0 = rss[tl], mu1 = mus[tl + 8], rs1 = rss[tl + 8];

    float acc[8][4];
    #pragma unroll
    for (int i = 0; i < 8; i++) {
        #pragma unroll
        for (int j = 0; j < 4; j++) acc[i][j] = 0.f;
    }

    for (int kc = 0; kc < 4; kc++) {
        const int c0 = kc * 64;
        __syncthreads();
        {
            const int c4 = (tid & 15) * 4;
            const float* wsrc = qkv_w + (size_t)n0 * 256 + c0 + c4;
            #pragma unroll
            for (int n = tid >> 4; n < 128; n += 16) {
                const float4 v = *(const float4*)(wsrc + (size_t)n * 256);
                float* d = ws + n * WS_STRIDE + c4;
                d[0] = __uint_as_float(f2tf32(v.x));
                d[1] = __uint_as_float(f2tf32(v.y));
                d[2] = __uint_as_float(f2tf32(v.z));
                d[3] = __uint_as_float(f2tf32(v.w));
            }
        }
        __syncthreads();
        #pragma unroll
        for (int kk = 0; kk < 8; kk++) {
            const int c = c0 + kk * 8 + tig;
            const float wc = lw[c], bc = lb[c], wc4 = lw[c + 4], bc4 = lb[c + 4];
            unsigned a[4];
            a[0] = f2tf32((xs[c * XS_STRIDE + tl]           - mu0) * rs0 * wc  + bc);
            a[1] = f2tf32((xs[c * XS_STRIDE + tl + 8]       - mu1) * rs1 * wc  + bc);
            a[2] = f2tf32((xs[(c + 4) * XS_STRIDE + tl]     - mu0) * rs0 * wc4 + bc4);
            a[3] = f2tf32((xs[(c + 4) * XS_STRIDE + tl + 8] - mu1) * rs1 * wc4 + bc4);
            #pragma unroll
            for (int nt = 0; nt < 8; nt++) {
                const int nl = wn * 64 + nt * 8 + gid;
                unsigned bf[2];
                bf[0] = __float_as_uint(ws[nl * WS_STRIDE + kk * 8 + tig]);
                bf[1] = __float_as_uint(ws[nl * WS_STRIDE + kk * 8 + tig + 4]);
                mma_tf32(acc[nt], a, bf);
            }
        }
    }

    // Epilogue: bias, fold (scale*log2e) into Q, pack fp16 fragment pairs
    const bool is_q = (n0 < 256);
    const int trow = t0 + tl;
    #pragma unroll
    for (int nt = 0; nt < 8; nt++) {
        const int ng = n0 + wn * 64 + nt * 8 + 2 * tig;
        const int nq = is_q ? ng : (ng - 256);
        const int h = nq >> 5, d = nq & 31;
        const int bh = b * 8 + h;
        const float bias0 = qkv_b[ng], bias1 = qkv_b[ng + 1];
        float v0 = acc[nt][0] + bias0, v1 = acc[nt][1] + bias1;
        float v2 = acc[nt][2] + bias0, v3 = acc[nt][3] + bias1;
        if (is_q) {
            v0 *= QSCALE; v1 *= QSCALE; v2 *= QSCALE; v3 *= QSCALE;
            store_qfrag_h2(bh, trow,     d, pack_h2(v0, v1));
            store_qfrag_h2(bh, trow + 8, d, pack_h2(v2, v3));
        } else {
            store_kfrag_h2(bh, trow,     d, pack_h2(v0, v1));
            store_kfrag_h2(bh, trow + 8, d, pack_h2(v2, v3));
        }
    }
}

// ===================== Kernel 2: fp16 mma + cp.async 4-stage pipeline ============
// 128 thr / 4 warps, 2x2 split: wm -> 32 rows (2 m-frags), wn -> 32 of 64 chunk
// cols. fp16 m16n8k16: half the MMAs, half the K bytes (chunk = 4KB), afr = 16
// regs. K chunks gmem -> smem via cp.async.cg, 4 stages x 4KB, depth 3.
// One uint4 LDS.128 per 8-col group = the full k=32 B fragment set.
// Single 50-iter loop: gi<25 pass 1 (row sums of exp2), gi>=25 pass 2 (recompute
// + normalized store). Reduction inline at gi==24.
#define NSTAGE 4

__global__ void __launch_bounds__(128, 7) attn_kernel(float* __restrict__ out)
{
    __shared__ uint4 Ks[NSTAGE][256];      // 4 x 4KB chunk stages
    __shared__ float red[2][64];

    const int tid = threadIdx.x;
    const int warp = tid >> 5, lane = tid & 31;
    const int gid = lane >> 2, tig = lane & 3;
    const int wm = warp >> 1, wn = warp & 1;
    const int bh = blockIdx.y;
    const int t0 = blockIdx.x * 64;

    // A fragments: 2 m-frags x 2 k-blocks, constant for whole kernel (4x LDG.128)
    unsigned afr[2][2][4];
    #pragma unroll
    for (int mf = 0; mf < 2; mf++) {
        const int rt = blockIdx.x * 4 + wm * 2 + mf;
        const uint4* qf = (const uint4*)g_Qf + ((size_t)bh * 100 + rt) * 2 * 32 + lane;
        #pragma unroll
        for (int kb = 0; kb < 2; kb++) {
            const uint4 v = qf[kb * 32];
            afr[mf][kb][0] = v.x; afr[mf][kb][1] = v.y;
            afr[mf][kb][2] = v.z; afr[mf][kb][3] = v.w;
        }
    }

    const uint4* ksrc = (const uint4*)g_Kf + (size_t)bh * 25 * 256;
    const unsigned ks_u32 = (unsigned)__cvta_generic_to_shared(&Ks[0][0]) + tid * 16;

    // prefetch chunk c into stage s: 2 coalesced 16B cp.async per thread (4KB/CTA)
    #define PREFETCH(c, s) {                                                  \
        const unsigned d_ = ks_u32 + (s) * 4096;                              \
        const uint4* s_ = ksrc + (size_t)(c) * 256 + tid;                     \
        cp_async16(d_,        s_);                                            \
        cp_async16(d_ + 2048, s_ + 128);                                      \
        asm volatile("cp.async.commit_group;"); }

    // one 8-col group: kf = full k=32 B fragments; 4 fp16 MMAs
    #define MMA_GROUP(kf)                                                     \
        const unsigned b0[2] = {(kf).x, (kf).y};                              \
        const unsigned b1[2] = {(kf).z, (kf).w};                              \
        float c0[4] = {0.f,0.f,0.f,0.f}, c1[4] = {0.f,0.f,0.f,0.f};           \
        mma_f16(c0, afr[0][0], b0); mma_f16(c1, afr[1][0], b0);               \
        mma_f16(c0, afr[0][1], b1); mma_f16(c1, afr[1][1], b1);

    float sums[4] = {0.f, 0.f, 0.f, 0.f};
    float inv[4];
    float* const obase = out + ((size_t)bh * T + t0 + wm * 32 + gid) * T + 2 * tig;

    // prime 3 stages
    PREFETCH(0, 0)
    PREFETCH(1, 1)
    PREFETCH(2, 2)

    for (int gi = 0; gi < 50; gi++) {
        asm volatile("cp.async.wait_group 2;");
        __syncthreads();                       // chunk gi ready; oldest stage consumed
        {   // prefetch chunk gi+3 (wraps; tail wraps are harmless reloads)
            const int c3 = gi + 3;
            const int ch = (c3 >= 50) ? (c3 - 50) : (c3 >= 25 ? c3 - 25 : c3);
            PREFETCH(ch, c3 & 3)
        }
        const uint4* kb4 = Ks[gi & 3];
        if (gi < 25) {
            #pragma unroll
            for (int g = 0; g < 4; g++) {
                const int ntg = wn * 4 + g;
                const uint4 kf = kb4[ntg * 32 + lane];
                MMA_GROUP(kf)
                sums[0] += ex2(c0[0]) + ex2(c0[1]);
                sums[1] += ex2(c0[2]) + ex2(c0[3]);
                sums[2] += ex2(c1[0]) + ex2(c1[1]);
                sums[3] += ex2(c1[2]) + ex2(c1[3]);
            }
            if (gi == 24) {
                // cross-warp row-sum reduction (prefetches remain in flight)
                #pragma unroll
                for (int i = 0; i < 4; i++) {
                    sums[i] += __shfl_xor_sync(~0u, sums[i], 1);
                    sums[i] += __shfl_xor_sync(~0u, sums[i], 2);
                }
                if (tig == 0) {
                    #pragma unroll
                    for (int mf = 0; mf < 2; mf++) {
                        red[wn][wm * 32 + mf * 16 + gid]     = sums[mf * 2];
                        red[wn][wm * 32 + mf * 16 + 8 + gid] = sums[mf * 2 + 1];
                    }
                }
                __syncthreads();
                #pragma unroll
                for (int mf = 0; mf < 2; mf++) {
                    const int lr0 = wm * 32 + mf * 16 + gid;
                    inv[mf * 2]     = 1.0f / (red[0][lr0] + red[1][lr0]);
                    inv[mf * 2 + 1] = 1.0f / (red[0][lr0 + 8] + red[1][lr0 + 8]);
                }
            }
        } else {
            const int ci = gi - 25;
            #pragma unroll
            for (int g = 0; g < 4; g++) {
                const int ntg = wn * 4 + g;
                const uint4 kf = kb4[ntg * 32 + lane];
                MMA_GROUP(kf)
                float* pp = obase + ci * 64 + ntg * 8;
                *(float2*)pp            = make_float2(ex2(c0[0]) * inv[0], ex2(c0[1]) * inv[0]);
                *(float2*)(pp + 8 * T)  = make_float2(ex2(c0[2]) * inv[1], ex2(c0[3]) * inv[1]);
                *(float2*)(pp + 16 * T) = make_float2(ex2(c1[0]) * inv[2], ex2(c1[1]) * inv[2]);
                *(float2*)(pp + 24 * T) = make_float2(ex2(c1[2]) * inv[3], ex2(c1[3]) * inv[3]);
            }
        }
    }

    #undef PREFETCH
    #undef MMA_GROUP
}

extern "C" void kernel_launch(void* const* d_in, const int* in_sizes, int n_in,
                              void* d_out, int out_size)
{
    (void)in_sizes; (void)n_in; (void)out_size;
    const float* feat  = (const float*)d_in[0];
    const float* ln_w  = (const float*)d_in[1];
    const float* ln_b  = (const float*)d_in[2];
    const float* qkv_w = (const float*)d_in[3];
    const float* qkv_b = (const float*)d_in[4];
    float* out = (float*)d_out;

    cudaFuncSetAttribute(ln_qkv_kernel, cudaFuncAttributeMaxDynamicSharedMemorySize,
                         K1_SMEM_FLOATS * 4);

    ln_qkv_kernel<<<dim3(4, 200), 256, K1_SMEM_FLOATS * 4>>>(feat, ln_w, ln_b, qkv_w, qkv_b);
    attn_kernel<<<dim3(25, 64), 128>>>(out);
}

// round 12
// speedup vs baseline: 1.7346x; 1.1219x over previous
#include <cuda_runtime.h>
#include <cuda_fp16.h>

#define T 1600
#define BH 64
#define HD 32
// softmax scale * log2(e): scores are computed in exp2 domain
#define QSCALE (0.17677669529663687f * 1.4426950408889634f)

// Pre-fragmented Q/K scratch in fp16 mma fragment order (m16n8k16).
// Qf: [bh][rt=t/16][kb=d/16][lane][reg]  reg = colhalf*2 + rowhalf (a0..a3)
// Kf: [bh][si=t/64][nt][lane][reg]       reg = kb*2 + bhalf       (b0,b1 per kb)
static __device__ unsigned g_Qf[(size_t)BH * 100 * 2 * 32 * 4];
static __device__ unsigned g_Kf[(size_t)BH * 25 * 8 * 32 * 4];

__device__ __forceinline__ unsigned pack_h2(float a, float b) {
    __half2 h = __floats2half2_rn(a, b);   // lo = a (lower k/col index)
    return *(unsigned*)&h;
}

__device__ __forceinline__ float ex2(float x) {
    float y;
    asm("ex2.approx.ftz.f32 %0, %1;" : "=f"(y) : "f"(x));
    return y;
}

// pair exp2 through the f16x2 MUFU path (pass-1 sums only: per-element fp16
// error ~5e-4 is suppressed by 1/sqrt(1600) in the row sum)
__device__ __forceinline__ float2 exp2_pair(float a, float b) {
    __half2 h = __floats2half2_rn(a, b);
    unsigned hu = *(unsigned*)&h;
    unsigned r;
    asm("ex2.approx.f16x2 %0, %1;" : "=r"(r) : "r"(hu));
    return __half22float2(*(__half2*)&r);
}

// fp16 mma m16n8k16, fp32 accum
__device__ __forceinline__ void mma_f16(float c[4], const unsigned a[4], const unsigned b[2]) {
    asm volatile(
        "mma.sync.aligned.m16n8k16.row.col.f32.f16.f16.f32 "
        "{%0,%1,%2,%3}, {%4,%5,%6,%7}, {%8,%9}, {%0,%1,%2,%3};\n"
        : "+f"(c[0]), "+f"(c[1]), "+f"(c[2]), "+f"(c[3])
        : "r"(a[0]), "r"(a[1]), "r"(a[2]), "r"(a[3]), "r"(b[0]), "r"(b[1]));
}

__device__ __forceinline__ void cp_async16(unsigned smem_addr, const void* gptr) {
    asm volatile("cp.async.cg.shared.global [%0], [%1], 16;"
                 :: "r"(smem_addr), "l"(gptr));
}

// store half2 (dims d, d+1; d even) of Q row t
__device__ __forceinline__ void store_qfrag_h2(int bh, int t, int d, unsigned h2) {
    const int rt = t >> 4, gid = t & 7, rhalf = (t >> 3) & 1;
    const int kb = d >> 4, dd = d & 15;
    const int colhalf = dd >> 3, tig = (dd & 7) >> 1;
    g_Qf[(((size_t)bh * 100 + rt) * 2 + kb) * 128 + (gid * 4 + tig) * 4 + colhalf * 2 + rhalf] = h2;
}

// store half2 (dims d, d+1) of K row (token) t
__device__ __forceinline__ void store_kfrag_h2(int bh, int t, int d, unsigned h2) {
    const int si = t >> 6, nt = (t >> 3) & 7, gid = t & 7;
    const int kb = d >> 4, dd = d & 15;
    const int bhalf = dd >> 3, tig = (dd & 7) >> 1;
    g_Kf[((((size_t)bh * 25 + si) * 8 + nt) * 32 + gid * 4 + tig) * 4 + kb * 2 + bhalf] = h2;
}

// ===================== Kernel 1: LayerNorm + QKV projection (Q,K only) =============
// fp16 end-to-end: x and W staged in smem as half (57.9KB total -> 3 CTAs/SM vs
// 2 before), score-path mma is m16n8k16 fp16 (half the mma + b-frag LDS count).
#define XS_HALFS 72            // halves per c-row (conflict-free a-frag loads)
#define WS_U32S 36             // half2 per n-row (gid*4+tig banks, conflict-free)
#define K1_SMEM_BYTES (256 * XS_HALFS * 2 + 128 * WS_U32S * 4 + 1024 + 1024 + 256 + 256)

__global__ void __launch_bounds__(256, 3) ln_qkv_kernel(
    const float* __restrict__ feat, const float* __restrict__ ln_w,
    const float* __restrict__ ln_b, const float* __restrict__ qkv_w,
    const float* __restrict__ qkv_b)
{
    extern __shared__ char sm1[];
    __half*   xs = (__half*)sm1;                                   // [256][72]
    unsigned* ws = (unsigned*)(sm1 + 256 * XS_HALFS * 2);          // [128][36] half2
    float*    lw = (float*)(sm1 + 256 * XS_HALFS * 2 + 128 * WS_U32S * 4);
    float*    lb  = lw + 256;
    float*    mus = lb + 256;
    float*    rss = mus + 64;

    const int tid = threadIdx.x;
    const int n0 = blockIdx.x * 128;        // 0,128 -> Q ; 256,384 -> K
    const int tb = blockIdx.y;              // 0..199
    const int b  = tb / 25;
    const int t0 = (tb % 25) * 64;

    // Load x tile (feat[b][c][t0..t0+63]) into fp16 smem, coalesced float4
    {
        const float* src = feat + ((size_t)b * 256) * T + t0;
        const int c4 = (tid & 15) * 4;
        #pragma unroll 4
        for (int c = tid >> 4; c < 256; c += 16) {
            const float4 v = *(const float4*)(src + (size_t)c * T + c4);
            __half2* d = (__half2*)(xs + c * XS_HALFS + c4);
            d[0] = __floats2half2_rn(v.x, v.y);
            d[1] = __floats2half2_rn(v.z, v.w);
        }
        lw[tid] = ln_w[tid];
        lb[tid] = ln_b[tid];
    }
    __syncthreads();

    // LN stats: 4 threads per token (fp32 from fp16 x; error negligible)
    {
        const int t = tid >> 2, g = tid & 3;
        float s = 0.f, sq = 0.f;
        for (int c = g; c < 256; c += 4) {
            const float v = __half2float(xs[c * XS_HALFS + t]);
            s += v; sq += v * v;
        }
        s += __shfl_xor_sync(~0u, s, 1); sq += __shfl_xor_sync(~0u, sq, 1);
        s += __shfl_xor_sync(~0u, s, 2); sq += __shfl_xor_sync(~0u, sq, 2);
        if (g == 0) {
            const float mu = s * (1.f / 256.f);
            mus[t] = mu;
            rss[t] = rsqrtf(sq * (1.f / 256.f) - mu * mu + 1e-6f);
        }
    }
    __syncthreads();

    const int warp = tid >> 5, lane = tid & 31;
    const int wm = warp >> 1, wn = warp & 1;
    const int gid = lane >> 2, tig = lane & 3;
    const int tl = wm * 16 + gid;
    const float rs0 = rss[tl], mrs0 = mus[tl] * rs0;
    const float rs1 = rss[tl + 8], mrs1 = mus[tl + 8] * rs1;

    float acc[8][4];
    #pragma unroll
    for (int i = 0; i < 8; i++) {
        #pragma unroll
        for (int j = 0; j < 4; j++) acc[i][j] = 0.f;
    }

    for (int kc = 0; kc < 4; kc++) {
        const int c0 = kc * 64;
        __syncthreads();   // previous ws fully consumed
        {   // stage W chunk as packed half2
            const int c4 = (tid & 15) * 4;
            const float* wsrc = qkv_w + (size_t)n0 * 256 + c0 + c4;
            #pragma unroll
            for (int n = tid >> 4; n < 128; n += 16) {
                const float4 v = *(const float4*)(wsrc + (size_t)n * 256);
                unsigned* d = ws + n * WS_U32S + (c4 >> 1);
                d[0] = pack_h2(v.x, v.y);
                d[1] = pack_h2(v.z, v.w);
            }
        }
        __syncthreads();
        #pragma unroll
        for (int kk = 0; kk < 4; kk++) {       // 4 k16-blocks per 64-chunk
            const int cb = c0 + kk * 16 + 2 * tig;
            float va0[4], va1[4];              // rows tl / tl+8; cols cb,cb+1,cb+8,cb+9
            #pragma unroll
            for (int j = 0; j < 4; j++) {
                const int c = cb + (j >> 1) * 8 + (j & 1);
                const float w = lw[c], bb = lb[c];
                const float x0 = __half2float(xs[c * XS_HALFS + tl]);
                const float x1 = __half2float(xs[c * XS_HALFS + tl + 8]);
                va0[j] = fmaf(fmaf(x0, rs0, -mrs0), w, bb);
                va1[j] = fmaf(fmaf(x1, rs1, -mrs1), w, bb);
            }
            unsigned a[4];
            a[0] = pack_h2(va0[0], va0[1]);
            a[1] = pack_h2(va1[0], va1[1]);
            a[2] = pack_h2(va0[2], va0[3]);
            a[3] = pack_h2(va1[2], va1[3]);
            #pragma unroll
            for (int nt = 0; nt < 8; nt++) {
                const int nl = wn * 64 + nt * 8 + gid;
                unsigned bf[2];
                bf[0] = ws[nl * WS_U32S + kk * 8 + tig];
                bf[1] = ws[nl * WS_U32S + kk * 8 + 4 + tig];
                mma_f16(acc[nt], a, bf);
            }
        }
    }

    // Epilogue: bias, fold (scale*log2e) into Q, pack fp16 fragment pairs
    const bool is_q = (n0 < 256);
    const int trow = t0 + tl;
    #pragma unroll
    for (int nt = 0; nt < 8; nt++) {
        const int ng = n0 + wn * 64 + nt * 8 + 2 * tig;
        const int nq = is_q ? ng : (ng - 256);
        const int h = nq >> 5, d = nq & 31;
        const int bh = b * 8 + h;
        const float bias0 = qkv_b[ng], bias1 = qkv_b[ng + 1];
        float v0 = acc[nt][0] + bias0, v1 = acc[nt][1] + bias1;
        float v2 = acc[nt][2] + bias0, v3 = acc[nt][3] + bias1;
        if (is_q) {
            v0 *= QSCALE; v1 *= QSCALE; v2 *= QSCALE; v3 *= QSCALE;
            store_qfrag_h2(bh, trow,     d, pack_h2(v0, v1));
            store_qfrag_h2(bh, trow + 8, d, pack_h2(v2, v3));
        } else {
            store_kfrag_h2(bh, trow,     d, pack_h2(v0, v1));
            store_kfrag_h2(bh, trow + 8, d, pack_h2(v2, v3));
        }
    }
}

// ===================== Kernel 2: fp16 mma + cp.async 4-stage pipeline ============
// 128 thr / 4 warps, 2x2 split: wm -> 32 rows (2 m-frags), wn -> 32 of 64 chunk
// cols. fp16 m16n8k16. K chunks gmem -> smem via cp.async.cg, 4 stages x 4KB,
// depth 3. One uint4 LDS.128 per 8-col group. Pass 1 (gi<25): row sums of exp2
// via f16x2 MUFU (2 exps/instr). Pass 2: fp32 exp2, normalize, stream out.
#define NSTAGE 4

__global__ void __launch_bounds__(128, 7) attn_kernel(float* __restrict__ out)
{
    __shared__ uint4 Ks[NSTAGE][256];      // 4 x 4KB chunk stages
    __shared__ float red[2][64];

    const int tid = threadIdx.x;
    const int warp = tid >> 5, lane = tid & 31;
    const int gid = lane >> 2, tig = lane & 3;
    const int wm = warp >> 1, wn = warp & 1;
    const int bh = blockIdx.y;
    const int t0 = blockIdx.x * 64;

    // A fragments: 2 m-frags x 2 k-blocks, constant for whole kernel (4x LDG.128)
    unsigned afr[2][2][4];
    #pragma unroll
    for (int mf = 0; mf < 2; mf++) {
        const int rt = blockIdx.x * 4 + wm * 2 + mf;
        const uint4* qf = (const uint4*)g_Qf + ((size_t)bh * 100 + rt) * 2 * 32 + lane;
        #pragma unroll
        for (int kb = 0; kb < 2; kb++) {
            const uint4 v = qf[kb * 32];
            afr[mf][kb][0] = v.x; afr[mf][kb][1] = v.y;
            afr[mf][kb][2] = v.z; afr[mf][kb][3] = v.w;
        }
    }

    const uint4* ksrc = (const uint4*)g_Kf + (size_t)bh * 25 * 256;
    const unsigned ks_u32 = (unsigned)__cvta_generic_to_shared(&Ks[0][0]) + tid * 16;

    // prefetch chunk c into stage s: 2 coalesced 16B cp.async per thread (4KB/CTA)
    #define PREFETCH(c, s) {                                                  \
        const unsigned d_ = ks_u32 + (s) * 4096;                              \
        const uint4* s_ = ksrc + (size_t)(c) * 256 + tid;                     \
        cp_async16(d_,        s_);                                            \
        cp_async16(d_ + 2048, s_ + 128);                                      \
        asm volatile("cp.async.commit_group;"); }

    // one 8-col group: kf = full k=32 B fragment set; 4 fp16 MMAs
    #define MMA_GROUP(kf)                                                     \
        const unsigned b0[2] = {(kf).x, (kf).y};                              \
        const unsigned b1[2] = {(kf).z, (kf).w};                              \
        float c0[4] = {0.f,0.f,0.f,0.f}, c1[4] = {0.f,0.f,0.f,0.f};           \
        mma_f16(c0, afr[0][0], b0); mma_f16(c1, afr[1][0], b0);               \
        mma_f16(c0, afr[0][1], b1); mma_f16(c1, afr[1][1], b1);

    float sums[4] = {0.f, 0.f, 0.f, 0.f};
    float inv[4];
    float* const obase = out + ((size_t)bh * T + t0 + wm * 32 + gid) * T + 2 * tig;

    // prime 3 stages
    PREFETCH(0, 0)
    PREFETCH(1, 1)
    PREFETCH(2, 2)

    for (int gi = 0; gi < 50; gi++) {
        asm volatile("cp.async.wait_group 2;");
        __syncthreads();                       // chunk gi ready; oldest stage consumed
        {   // prefetch chunk gi+3 (wraps; tail wraps are harmless reloads)
            const int c3 = gi + 3;
            const int ch = (c3 >= 50) ? (c3 - 50) : (c3 >= 25 ? c3 - 25 : c3);
            PREFETCH(ch, c3 & 3)
        }
        const uint4* kb4 = Ks[gi & 3];
        if (gi < 25) {
            #pragma unroll
            for (int g = 0; g < 4; g++) {
                const int ntg = wn * 4 + g;
                const uint4 kf = kb4[ntg * 32 + lane];
                MMA_GROUP(kf)
                const float2 e0 = exp2_pair(c0[0], c0[1]);
                const float2 e1 = exp2_pair(c0[2], c0[3]);
                const float2 e2 = exp2_pair(c1[0], c1[1]);
                const float2 e3 = exp2_pair(c1[2], c1[3]);
                sums[0] += e0.x + e0.y;
                sums[1] += e1.x + e1.y;
                sums[2] += e2.x + e2.y;
                sums[3] += e3.x + e3.y;
            }
            if (gi == 24) {
                // cross-warp row-sum reduction (prefetches remain in flight)
                #pragma unroll
                for (int i = 0; i < 4; i++) {
                    sums[i] += __shfl_xor_sync(~0u, sums[i], 1);
                    sums[i] += __shfl_xor_sync(~0u, sums[i], 2);
                }
                if (tig == 0) {
                    #pragma unroll
                    for (int mf = 0; mf < 2; mf++) {
                        red[wn][wm * 32 + mf * 16 + gid]     = sums[mf * 2];
                        red[wn][wm * 32 + mf * 16 + 8 + gid] = sums[mf * 2 + 1];
                    }
                }
                __syncthreads();
                #pragma unroll
                for (int mf = 0; mf < 2; mf++) {
                    const int lr0 = wm * 32 + mf * 16 + gid;
                    inv[mf * 2]     = 1.0f / (red[0][lr0] + red[1][lr0]);
                    inv[mf * 2 + 1] = 1.0f / (red[0][lr0 + 8] + red[1][lr0 + 8]);
                }
            }
        } else {
            const int ci = gi - 25;
            #pragma unroll
            for (int g = 0; g < 4; g++) {
                const int ntg = wn * 4 + g;
                const uint4 kf = kb4[ntg * 32 + lane];
                MMA_GROUP(kf)
                float* pp = obase + ci * 64 + ntg * 8;
                *(float2*)pp            = make_float2(ex2(c0[0]) * inv[0], ex2(c0[1]) * inv[0]);
                *(float2*)(pp + 8 * T)  = make_float2(ex2(c0[2]) * inv[1], ex2(c0[3]) * inv[1]);
                *(float2*)(pp + 16 * T) = make_float2(ex2(c1[0]) * inv[2], ex2(c1[1]) * inv[2]);
                *(float2*)(pp + 24 * T) = make_float2(ex2(c1[2]) * inv[3], ex2(c1[3]) * inv[3]);
            }
        }
    }

    #undef PREFETCH
    #undef MMA_GROUP
}

extern "C" void kernel_launch(void* const* d_in, const int* in_sizes, int n_in,
                              void* d_out, int out_size)
{
    (void)in_sizes; (void)n_in; (void)out_size;
    const float* feat  = (const float*)d_in[0];
    const float* ln_w  = (const float*)d_in[1];
    const float* ln_b  = (const float*)d_in[2];
    const float* qkv_w = (const float*)d_in[3];
    const float* qkv_b = (const float*)d_in[4];
    float* out = (float*)d_out;

    cudaFuncSetAttribute(ln_qkv_kernel, cudaFuncAttributeMaxDynamicSharedMemorySize,
                         K1_SMEM_BYTES);

    ln_qkv_kernel<<<dim3(4, 200), 256, K1_SMEM_BYTES>>>(feat, ln_w, ln_b, qkv_w, qkv_b);
    attn_kernel<<<dim3(25, 64), 128>>>(out);
}

// round 13
// speedup vs baseline: 1.7740x; 1.0227x over previous
#include <cuda_runtime.h>
#include <cuda_fp16.h>

#define T 1600
#define BH 64
#define HD 32
// softmax scale * log2(e): scores are computed in exp2 domain
#define QSCALE (0.17677669529663687f * 1.4426950408889634f)

// Pre-fragmented Q/K scratch in fp16 mma fragment order (m16n8k16).
static __device__ unsigned g_Qf[(size_t)BH * 100 * 2 * 32 * 4];
static __device__ unsigned g_Kf[(size_t)BH * 25 * 8 * 32 * 4];
// LN-folded projection weights (fp16) and bias (fp32), built by prep_kernel
static __device__ __half g_Wh[512 * 256];
static __device__ float  g_bq[512];

__device__ __forceinline__ unsigned pack_h2(float a, float b) {
    __half2 h = __floats2half2_rn(a, b);
    return *(unsigned*)&h;
}

// pair exp2 through the f16x2 MUFU path (2 exps per MUFU op). Per-element fp16
// error ~5e-4 rel; acceptable against the 1e-3 gate on top of the fp16-GEMM base.
__device__ __forceinline__ float2 exp2_pair(float a, float b) {
    __half2 h = __floats2half2_rn(a, b);
    unsigned hu = *(unsigned*)&h;
    unsigned r;
    asm("ex2.approx.f16x2 %0, %1;" : "=r"(r) : "r"(hu));
    return __half22float2(*(__half2*)&r);
}

// fp16 mma m16n8k16, fp32 accum
__device__ __forceinline__ void mma_f16(float c[4], const unsigned a[4], const unsigned b[2]) {
    asm volatile(
        "mma.sync.aligned.m16n8k16.row.col.f32.f16.f16.f32 "
        "{%0,%1,%2,%3}, {%4,%5,%6,%7}, {%8,%9}, {%0,%1,%2,%3};\n"
        : "+f"(c[0]), "+f"(c[1]), "+f"(c[2]), "+f"(c[3])
        : "r"(a[0]), "r"(a[1]), "r"(a[2]), "r"(a[3]), "r"(b[0]), "r"(b[1]));
}

__device__ __forceinline__ void cp_async16(unsigned smem_addr, const void* gptr) {
    asm volatile("cp.async.cg.shared.global [%0], [%1], 16;"
                 :: "r"(smem_addr), "l"(gptr));
}

__device__ __forceinline__ void store_qfrag_h2(int bh, int t, int d, unsigned h2) {
    const int rt = t >> 4, gid = t & 7, rhalf = (t >> 3) & 1;
    const int kb = d >> 4, dd = d & 15;
    const int colhalf = dd >> 3, tig = (dd & 7) >> 1;
    g_Qf[(((size_t)bh * 100 + rt) * 2 + kb) * 128 + (gid * 4 + tig) * 4 + colhalf * 2 + rhalf] = h2;
}

__device__ __forceinline__ void store_kfrag_h2(int bh, int t, int d, unsigned h2) {
    const int si = t >> 6, nt = (t >> 3) & 7, gid = t & 7;
    const int kb = d >> 4, dd = d & 15;
    const int bhalf = dd >> 3, tig = (dd & 7) >> 1;
    g_Kf[((((size_t)bh * 25 + si) * 8 + nt) * 32 + gid * 4 + tig) * 4 + kb * 2 + bhalf] = h2;
}

// ===================== Kernel 0: fold LN gamma/beta into W and bias ===============
// W'[n][c] = W[n][c]*lnw[c] (fp16);  b'[n] = sum_c W[n][c]*lnb[c] + b[n]
__global__ void __launch_bounds__(32) prep_kernel(
    const float* __restrict__ qkv_w, const float* __restrict__ qkv_b,
    const float* __restrict__ ln_w, const float* __restrict__ ln_b)
{
    const int n = blockIdx.x;           // 0..511
    const int lane = threadIdx.x;
    const float* wr = qkv_w + (size_t)n * 256;
    float partial = 0.f;
    #pragma unroll
    for (int j = 0; j < 8; j++) {
        const int c = lane + j * 32;
        const float w = wr[c];
        g_Wh[n * 256 + c] = __float2half(w * ln_w[c]);
        partial += w * ln_b[c];
    }
    #pragma unroll
    for (int o = 16; o; o >>= 1) partial += __shfl_xor_sync(~0u, partial, o);
    if (lane == 0) g_bq[n] = partial + qkv_b[n];
}

// ===================== Kernel 1: LayerNorm + QKV projection (Q,K only) =============
// fp16 end-to-end; W' (pre-fp16) streamed via cp.async 2-stage pipeline so W
// loads overlap mma of the previous k-chunk. a-frag is one FMA per element
// (LN folded into W/bias by prep_kernel).
#define XS_HALFS 72            // halves per c-row (conflict-free a-frag loads)
#define WS_HALFS 72            // halves per n-row per stage (conflict-free b-frags)
#define K1_SMEM_BYTES (256 * XS_HALFS * 2 + 2 * 128 * WS_HALFS * 2 + 512)

__global__ void __launch_bounds__(256, 3) ln_qkv_kernel(const float* __restrict__ feat)
{
    extern __shared__ char sm1[];
    __half* xs = (__half*)sm1;                                      // [256][72]
    __half* wsh = (__half*)(sm1 + 256 * XS_HALFS * 2);              // [2][128][72]
    float*  mus = (float*)(sm1 + 256 * XS_HALFS * 2 + 2 * 128 * WS_HALFS * 2);
    float*  rss = mus + 64;

    const int tid = threadIdx.x;
    const int n0 = blockIdx.x * 128;        // 0,128 -> Q ; 256,384 -> K
    const int tb = blockIdx.y;              // 0..199
    const int b  = tb / 25;
    const int t0 = (tb % 25) * 64;

    const unsigned ws_u32 = (unsigned)__cvta_generic_to_shared(wsh);

    // prefetch W' chunk kc into stage s: 128 rows x 128B, row stride 144B
    #define PREW(kc, s) {                                                       \
        _Pragma("unroll")                                                       \
        for (int j = 0; j < 4; j++) {                                           \
            const int ch = tid + j * 256;          /* 0..1023 */                \
            const int r = ch >> 3, cj = ch & 7;                                 \
            cp_async16(ws_u32 + (s) * (128 * WS_HALFS * 2) + r * (WS_HALFS * 2) \
                       + cj * 16,                                               \
                       (const char*)(g_Wh + (size_t)(n0 + r) * 256 + (kc) * 64) \
                       + cj * 16);                                              \
        }                                                                       \
        asm volatile("cp.async.commit_group;"); }

    PREW(0, 0)

    // Load x tile (feat[b][c][t0..t0+63]) into fp16 smem, coalesced float4
    {
        const float* src = feat + ((size_t)b * 256) * T + t0;
        const int c4 = (tid & 15) * 4;
        #pragma unroll 4
        for (int c = tid >> 4; c < 256; c += 16) {
            const float4 v = *(const float4*)(src + (size_t)c * T + c4);
            __half2* d = (__half2*)(xs + c * XS_HALFS + c4);
            d[0] = __floats2half2_rn(v.x, v.y);
            d[1] = __floats2half2_rn(v.z, v.w);
        }
    }
    __syncthreads();

    // LN stats: 4 threads per token
    {
        const int t = tid >> 2, g = tid & 3;
        float s = 0.f, sq = 0.f;
        for (int c = g; c < 256; c += 4) {
            const float v = __half2float(xs[c * XS_HALFS + t]);
            s += v; sq += v * v;
        }
        s += __shfl_xor_sync(~0u, s, 1); sq += __shfl_xor_sync(~0u, sq, 1);
        s += __shfl_xor_sync(~0u, s, 2); sq += __shfl_xor_sync(~0u, sq, 2);
        if (g == 0) {
            const float mu = s * (1.f / 256.f);
            mus[t] = mu;
            rss[t] = rsqrtf(sq * (1.f / 256.f) - mu * mu + 1e-6f);
        }
    }
    __syncthreads();

    const int warp = tid >> 5, lane = tid & 31;
    const int wm = warp >> 1, wn = warp & 1;
    const int gid = lane >> 2, tig = lane & 3;
    const int tl = wm * 16 + gid;
    const float rs0 = rss[tl], mrs0 = mus[tl] * rs0;
    const float rs1 = rss[tl + 8], mrs1 = mus[tl + 8] * rs1;

    float acc[8][4];
    #pragma unroll
    for (int i = 0; i < 8; i++) {
        #pragma unroll
        for (int j = 0; j < 4; j++) acc[i][j] = 0.f;
    }

    const unsigned* ws32 = (const unsigned*)wsh;

    for (int kc = 0; kc < 4; kc++) {
        // all warps done with stage (kc-2)&1 == kc&1 before refilling it
        if (kc + 1 < 4) PREW(kc + 1, (kc + 1) & 1)
        if (kc + 1 < 4) { asm volatile("cp.async.wait_group 1;"); }
        else            { asm volatile("cp.async.wait_group 0;"); }
        __syncthreads();
        const unsigned* wstage = ws32 + (kc & 1) * (128 * WS_HALFS / 2);
        #pragma unroll
        for (int kk = 0; kk < 4; kk++) {       // 4 k16-blocks per 64-chunk
            const int cb = kc * 64 + kk * 16 + 2 * tig;
            float va0[4], va1[4];              // rows tl/tl+8; cols cb,cb+1,cb+8,cb+9
            #pragma unroll
            for (int j = 0; j < 4; j++) {
                const int c = cb + (j >> 1) * 8 + (j & 1);
                const float x0 = __half2float(xs[c * XS_HALFS + tl]);
                const float x1 = __half2float(xs[c * XS_HALFS + tl + 8]);
                va0[j] = fmaf(x0, rs0, -mrs0);
                va1[j] = fmaf(x1, rs1, -mrs1);
            }
            unsigned a[4];
            a[0] = pack_h2(va0[0], va0[1]);
            a[1] = pack_h2(va1[0], va1[1]);
            a[2] = pack_h2(va0[2], va0[3]);
            a[3] = pack_h2(va1[2], va1[3]);
            #pragma unroll
            for (int nt = 0; nt < 8; nt++) {
                const int nl = wn * 64 + nt * 8 + gid;
                unsigned bf[2];
                bf[0] = wstage[nl * (WS_HALFS / 2) + kk * 8 + tig];
                bf[1] = wstage[nl * (WS_HALFS / 2) + kk * 8 + 4 + tig];
                mma_f16(acc[nt], a, bf);
            }
        }
        __syncthreads();   // stage kc fully consumed before next refill
    }

    // Epilogue: folded bias, fold (scale*log2e) into Q, pack fp16 fragment pairs
    const bool is_q = (n0 < 256);
    const int trow = t0 + tl;
    #pragma unroll
    for (int nt = 0; nt < 8; nt++) {
        const int ng = n0 + wn * 64 + nt * 8 + 2 * tig;
        const int nq = is_q ? ng : (ng - 256);
        const int h = nq >> 5, d = nq & 31;
        const int bh = b * 8 + h;
        const float bias0 = g_bq[ng], bias1 = g_bq[ng + 1];
        float v0 = acc[nt][0] + bias0, v1 = acc[nt][1] + bias1;
        float v2 = acc[nt][2] + bias0, v3 = acc[nt][3] + bias1;
        if (is_q) {
            v0 *= QSCALE; v1 *= QSCALE; v2 *= QSCALE; v3 *= QSCALE;
            store_qfrag_h2(bh, trow,     d, pack_h2(v0, v1));
            store_qfrag_h2(bh, trow + 8, d, pack_h2(v2, v3));
        } else {
            store_kfrag_h2(bh, trow,     d, pack_h2(v0, v1));
            store_kfrag_h2(bh, trow + 8, d, pack_h2(v2, v3));
        }
    }
    #undef PREW
}

// ===================== Kernel 2: fp16 mma + cp.async 4-stage pipeline ============
// Same structure as r12; pass 2 now also uses f16x2 MUFU exp (halves pass-2 MUFU).
#define NSTAGE 4

__global__ void __launch_bounds__(128, 7) attn_kernel(float* __restrict__ out)
{
    __shared__ uint4 Ks[NSTAGE][256];      // 4 x 4KB chunk stages
    __shared__ float red[2][64];

    const int tid = threadIdx.x;
    const int warp = tid >> 5, lane = tid & 31;
    const int gid = lane >> 2, tig = lane & 3;
    const int wm = warp >> 1, wn = warp & 1;
    const int bh = blockIdx.y;
    const int t0 = blockIdx.x * 64;

    unsigned afr[2][2][4];
    #pragma unroll
    for (int mf = 0; mf < 2; mf++) {
        const int rt = blockIdx.x * 4 + wm * 2 + mf;
        const uint4* qf = (const uint4*)g_Qf + ((size_t)bh * 100 + rt) * 2 * 32 + lane;
        #pragma unroll
        for (int kb = 0; kb < 2; kb++) {
            const uint4 v = qf[kb * 32];
            afr[mf][kb][0] = v.x; afr[mf][kb][1] = v.y;
            afr[mf][kb][2] = v.z; afr[mf][kb][3] = v.w;
        }
    }

    const uint4* ksrc = (const uint4*)g_Kf + (size_t)bh * 25 * 256;
    const unsigned ks_u32 = (unsigned)__cvta_generic_to_shared(&Ks[0][0]) + tid * 16;

    #define PREFETCH(c, s) {                                                  \
        const unsigned d_ = ks_u32 + (s) * 4096;                              \
        const uint4* s_ = ksrc + (size_t)(c) * 256 + tid;                     \
        cp_async16(d_,        s_);                                            \
        cp_async16(d_ + 2048, s_ + 128);                                      \
        asm volatile("cp.async.commit_group;"); }

    #define MMA_GROUP(kf)                                                     \
        const unsigned b0[2] = {(kf).x, (kf).y};                              \
        const unsigned b1[2] = {(kf).z, (kf).w};                              \
        float c0[4] = {0.f,0.f,0.f,0.f}, c1[4] = {0.f,0.f,0.f,0.f};           \
        mma_f16(c0, afr[0][0], b0); mma_f16(c1, afr[1][0], b0);               \
        mma_f16(c0, afr[0][1], b1); mma_f16(c1, afr[1][1], b1);

    float sums[4] = {0.f, 0.f, 0.f, 0.f};
    float inv[4];
    float* const obase = out + ((size_t)bh * T + t0 + wm * 32 + gid) * T + 2 * tig;

    PREFETCH(0, 0)
    PREFETCH(1, 1)
    PREFETCH(2, 2)

    for (int gi = 0; gi < 50; gi++) {
        asm volatile("cp.async.wait_group 2;");
        __syncthreads();
        {
            const int c3 = gi + 3;
            const int ch = (c3 >= 50) ? (c3 - 50) : (c3 >= 25 ? c3 - 25 : c3);
            PREFETCH(ch, c3 & 3)
        }
        const uint4* kb4 = Ks[gi & 3];
        if (gi < 25) {
            #pragma unroll
            for (int g = 0; g < 4; g++) {
                const int ntg = wn * 4 + g;
                const uint4 kf = kb4[ntg * 32 + lane];
                MMA_GROUP(kf)
                const float2 e0 = exp2_pair(c0[0], c0[1]);
                const float2 e1 = exp2_pair(c0[2], c0[3]);
                const float2 e2 = exp2_pair(c1[0], c1[1]);
                const float2 e3 = exp2_pair(c1[2], c1[3]);
                sums[0] += e0.x + e0.y;
                sums[1] += e1.x + e1.y;
                sums[2] += e2.x + e2.y;
                sums[3] += e3.x + e3.y;
            }
            if (gi == 24) {
                #pragma unroll
                for (int i = 0; i < 4; i++) {
                    sums[i] += __shfl_xor_sync(~0u, sums[i], 1);
                    sums[i] += __shfl_xor_sync(~0u, sums[i], 2);
                }
                if (tig == 0) {
                    #pragma unroll
                    for (int mf = 0; mf < 2; mf++) {
                        red[wn][wm * 32 + mf * 16 + gid]     = sums[mf * 2];
                        red[wn][wm * 32 + mf * 16 + 8 + gid] = sums[mf * 2 + 1];
                    }
                }
                __syncthreads();
                #pragma unroll
                for (int mf = 0; mf < 2; mf++) {
                    const int lr0 = wm * 32 + mf * 16 + gid;
                    inv[mf * 2]     = 1.0f / (red[0][lr0] + red[1][lr0]);
                    inv[mf * 2 + 1] = 1.0f / (red[0][lr0 + 8] + red[1][lr0 + 8]);
                }
            }
        } else {
            const int ci = gi - 25;
            #pragma unroll
            for (int g = 0; g < 4; g++) {
                const int ntg = wn * 4 + g;
                const uint4 kf = kb4[ntg * 32 + lane];
                MMA_GROUP(kf)
                const float2 e0 = exp2_pair(c0[0], c0[1]);
                const float2 e1 = exp2_pair(c0[2], c0[3]);
                const float2 e2 = exp2_pair(c1[0], c1[1]);
                const float2 e3 = exp2_pair(c1[2], c1[3]);
                float* pp = obase + ci * 64 + ntg * 8;
                *(float2*)pp            = make_float2(e0.x * inv[0], e0.y * inv[0]);
                *(float2*)(pp + 8 * T)  = make_float2(e1.x * inv[1], e1.y * inv[1]);
                *(float2*)(pp + 16 * T) = make_float2(e2.x * inv[2], e2.y * inv[2]);
                *(float2*)(pp + 24 * T) = make_float2(e3.x * inv[3], e3.y * inv[3]);
            }
        }
    }

    #undef PREFETCH
    #undef MMA_GROUP
}

extern "C" void kernel_launch(void* const* d_in, const int* in_sizes, int n_in,
                              void* d_out, int out_size)
{
    (void)in_sizes; (void)n_in; (void)out_size;
    const float* feat  = (const float*)d_in[0];
    const float* ln_w  = (const float*)d_in[1];
    const float* ln_b  = (const float*)d_in[2];
    const float* qkv_w = (const float*)d_in[3];
    const float* qkv_b = (const float*)d_in[4];
    float* out = (float*)d_out;

    cudaFuncSetAttribute(ln_qkv_kernel, cudaFuncAttributeMaxDynamicSharedMemorySize,
                         K1_SMEM_BYTES);

    prep_kernel<<<512, 32>>>(qkv_w, qkv_b, ln_w, ln_b);
    ln_qkv_kernel<<<dim3(4, 200), 256, K1_SMEM_BYTES>>>(feat);
    attn_kernel<<<dim3(25, 64), 128>>>(out);
}